// round 1
// baseline (speedup 1.0000x reference)
#include <cuda_runtime.h>
#include <cuda_bf16.h>

// Problem constants
#define B_   16
#define TE_  128
#define TD_  128
#define H_   256

// Scratch (device globals: no allocation allowed in kernel_launch)
__device__ float g_ortho[B_ * TE_ * H_];   // orthogonalized encoder [B, TE, H]
__device__ float g_was  [B_ * TE_ * H_];   // ortho @ W_a
__device__ float g_uah  [B_ * TD_ * H_];   // dec @ U_a

__device__ __forceinline__ float tanh_fast(float x) {
    float y;
    asm("tanh.approx.f32 %0, %1;" : "=f"(y) : "f"(x));
    return y;
}

// ---------------------------------------------------------------------------
// Kernel 1: Gram-Schmidt-style pass.
// out[t] = x[t] - ((x[t]*s)/(x[t]*x[t]))*x[t],  s = sum_{j<t} x[j]  (elementwise)
// One thread per (b,h) column; coalesced across h.
// ---------------------------------------------------------------------------
__global__ void ortho_kernel(const float* __restrict__ enc) {
    int idx = blockIdx.x * blockDim.x + threadIdx.x;     // 0 .. B_*H_-1
    int b = idx >> 8;
    int h = idx & (H_ - 1);
    const float* p = enc     + (b * TE_) * H_ + h;
    float*       q = g_ortho + (b * TE_) * H_ + h;
    float s = 0.0f;
#pragma unroll 4
    for (int t = 0; t < TE_; t++) {
        float x = p[t * H_];
        float o = x - __fdividef(x * s, x * x) * x;      // matches ref formula
        q[t * H_] = o;
        s += x;
    }
}

// ---------------------------------------------------------------------------
// Simple smem-tiled SGEMM:  C[M,256] = A[M,256] @ W[256,256]
// 64x64 tile per block, 256 threads, 4x4 microtile per thread.
// ---------------------------------------------------------------------------
__device__ __forceinline__ void gemm_body(const float* __restrict__ A,
                                          const float* __restrict__ W,
                                          float* __restrict__ C) {
    __shared__ float As[16][65];   // [k][m], padded vs 16-way bank conflict
    __shared__ float Bs[16][65];   // [k][n]
    const int bm = blockIdx.y * 64;
    const int bn = blockIdx.x * 64;
    const int tid = threadIdx.x;
    const int tr = tid >> 4;       // 0..15
    const int tc = tid & 15;       // 0..15

    float acc[4][4];
#pragma unroll
    for (int i = 0; i < 4; i++)
#pragma unroll
        for (int j = 0; j < 4; j++) acc[i][j] = 0.0f;

    for (int k0 = 0; k0 < 256; k0 += 16) {
#pragma unroll
        for (int i = tid; i < 1024; i += 256) {
            int m = i >> 4, kk = i & 15;
            As[kk][m] = A[(bm + m) * 256 + k0 + kk];
        }
#pragma unroll
        for (int i = tid; i < 1024; i += 256) {
            int kk = i >> 6, n = i & 63;
            Bs[kk][n] = W[(k0 + kk) * 256 + bn + n];
        }
        __syncthreads();
#pragma unroll
        for (int kk = 0; kk < 16; kk++) {
            float a[4], bb[4];
#pragma unroll
            for (int i = 0; i < 4; i++) a[i] = As[kk][tr * 4 + i];
#pragma unroll
            for (int j = 0; j < 4; j++) bb[j] = Bs[kk][tc * 4 + j];
#pragma unroll
            for (int i = 0; i < 4; i++)
#pragma unroll
                for (int j = 0; j < 4; j++)
                    acc[i][j] = fmaf(a[i], bb[j], acc[i][j]);
        }
        __syncthreads();
    }
#pragma unroll
    for (int i = 0; i < 4; i++)
#pragma unroll
        for (int j = 0; j < 4; j++)
            C[(bm + tr * 4 + i) * 256 + bn + tc * 4 + j] = acc[i][j];
}

__global__ __launch_bounds__(256) void gemm_was_kernel(const float* __restrict__ Wa) {
    gemm_body(g_ortho, Wa, g_was);
}

__global__ __launch_bounds__(256) void gemm_uah_kernel(const float* __restrict__ dec,
                                                       const float* __restrict__ Ua) {
    gemm_body(dec, Ua, g_uah);
}

// ---------------------------------------------------------------------------
// Kernel 3: fused energy + softmax + context.
// Block = (b, tile of 16 decoder positions). 256 threads = 8 warps.
// Each warp owns 2 decoder positions; uah & V_a live in registers.
// ---------------------------------------------------------------------------
__global__ __launch_bounds__(256) void attn_kernel(const float* __restrict__ Va,
                                                   float* __restrict__ c_out,
                                                   float* __restrict__ e_out) {
    const int b    = blockIdx.y;
    const int d0   = blockIdx.x * 16;
    const int tid  = threadIdx.x;
    const int warp = tid >> 5;
    const int lane = tid & 31;

    __shared__ float en_s[16][TE_];     // energies, then read for softmax
    __shared__ float pT_s[TE_][20];     // transposed probabilities [e][d], padded

    // Register preload: V_a and the warp's two uah rows (h = lane + 32*hh)
    float vreg[8], ureg[2][8];
#pragma unroll
    for (int hh = 0; hh < 8; hh++) {
        int h = lane + hh * 32;
        vreg[hh]    = Va[h];
        ureg[0][hh] = g_uah[((b * TD_) + (d0 + warp * 2 + 0)) * H_ + h];
        ureg[1][hh] = g_uah[((b * TD_) + (d0 + warp * 2 + 1)) * H_ + h];
    }

    const float* wbase = g_was + (b * TE_) * H_;

    // ---- Energies: the MUFU-bound core (128 e * 2 d * 8 h per warp) ----
    for (int e = 0; e < TE_; e++) {
        float w[8];
#pragma unroll
        for (int hh = 0; hh < 8; hh++)
            w[hh] = wbase[e * H_ + lane + hh * 32];
#pragma unroll
        for (int dd = 0; dd < 2; dd++) {
            float sum = 0.0f;
#pragma unroll
            for (int hh = 0; hh < 8; hh++) {
                float t = tanh_fast(w[hh] + ureg[dd][hh]);
                sum = fmaf(t, vreg[hh], sum);
            }
#pragma unroll
            for (int o = 16; o > 0; o >>= 1)
                sum += __shfl_xor_sync(0xffffffffu, sum, o);
            if (lane == 0) en_s[warp * 2 + dd][e] = sum;
        }
    }
    __syncthreads();

    // ---- Softmax over e (each warp: 2 rows of 128) ----
#pragma unroll
    for (int dd = 0; dd < 2; dd++) {
        int d = warp * 2 + dd;
        float v0 = en_s[d][lane];
        float v1 = en_s[d][lane + 32];
        float v2 = en_s[d][lane + 64];
        float v3 = en_s[d][lane + 96];
        float m = fmaxf(fmaxf(v0, v1), fmaxf(v2, v3));
#pragma unroll
        for (int o = 16; o > 0; o >>= 1)
            m = fmaxf(m, __shfl_xor_sync(0xffffffffu, m, o));
        float e0 = __expf(v0 - m), e1 = __expf(v1 - m);
        float e2 = __expf(v2 - m), e3 = __expf(v3 - m);
        float s = e0 + e1 + e2 + e3;
#pragma unroll
        for (int o = 16; o > 0; o >>= 1)
            s += __shfl_xor_sync(0xffffffffu, s, o);
        float inv = __fdividef(1.0f, s);
        float p0 = e0 * inv, p1 = e1 * inv, p2 = e2 * inv, p3 = e3 * inv;
        pT_s[lane     ][d] = p0;
        pT_s[lane + 32][d] = p1;
        pT_s[lane + 64][d] = p2;
        pT_s[lane + 96][d] = p3;
        float* eo = e_out + ((b * TD_) + (d0 + d)) * TE_;
        eo[lane]      = p0;
        eo[lane + 32] = p1;
        eo[lane + 64] = p2;
        eo[lane + 96] = p3;
    }
    __syncthreads();

    // ---- Context: c[d][h] = sum_e p[d][e] * ortho[b][e][h]; thread = h ----
    float acc[16];
#pragma unroll
    for (int d = 0; d < 16; d++) acc[d] = 0.0f;
    const float* eb = g_ortho + (b * TE_) * H_ + tid;
    for (int e = 0; e < TE_; e++) {
        float x = eb[e * H_];
        const float4* prow = reinterpret_cast<const float4*>(&pT_s[e][0]);
#pragma unroll
        for (int q = 0; q < 4; q++) {
            float4 p4 = prow[q];
            acc[q * 4 + 0] = fmaf(p4.x, x, acc[q * 4 + 0]);
            acc[q * 4 + 1] = fmaf(p4.y, x, acc[q * 4 + 1]);
            acc[q * 4 + 2] = fmaf(p4.z, x, acc[q * 4 + 2]);
            acc[q * 4 + 3] = fmaf(p4.w, x, acc[q * 4 + 3]);
        }
    }
#pragma unroll
    for (int d = 0; d < 16; d++)
        c_out[((b * TD_) + (d0 + d)) * H_ + tid] = acc[d];
}

// ---------------------------------------------------------------------------
extern "C" void kernel_launch(void* const* d_in, const int* in_sizes, int n_in,
                              void* d_out, int out_size) {
    const float* enc = (const float*)d_in[0];   // [16,128,256]
    const float* dec = (const float*)d_in[1];   // [16,128,256]
    const float* Wa  = (const float*)d_in[2];   // [256,256]
    const float* Ua  = (const float*)d_in[3];   // [256,256]
    const float* Va  = (const float*)d_in[4];   // [256,1]

    float* out   = (float*)d_out;
    float* c_out = out;                          // [16,128,256] = 524288
    float* e_out = out + B_ * TD_ * H_;          // [16,128,128] = 262144

    ortho_kernel<<<(B_ * H_) / 256, 256>>>(enc);
    gemm_was_kernel<<<dim3(4, 32), 256>>>(Wa);
    gemm_uah_kernel<<<dim3(4, 32), 256>>>(dec, Ua);
    attn_kernel<<<dim3(TD_ / 16, B_), 256>>>(Va, c_out, e_out);
}

// round 2
// speedup vs baseline: 1.3988x; 1.3988x over previous
#include <cuda_runtime.h>
#include <cuda_bf16.h>

// Problem constants
#define B_   16
#define TE_  128
#define TD_  128
#define H_   256

// Scratch (device globals: no allocation allowed in kernel_launch)
__device__ float g_ortho[B_ * TE_ * H_];   // orthogonalized encoder [B, TE, H]
__device__ float g_was  [B_ * TE_ * H_];   // ortho @ W_a
__device__ float g_uah  [B_ * TD_ * H_];   // dec @ U_a

__device__ __forceinline__ float tanh_fast(float x) {
    float y;
    asm("tanh.approx.f32 %0, %1;" : "=f"(y) : "f"(x));
    return y;
}

// ---------------------------------------------------------------------------
// Kernel 1: Gram-Schmidt-style pass (exclusive cumsum + projection formula).
// ---------------------------------------------------------------------------
__global__ void ortho_kernel(const float* __restrict__ enc) {
    int idx = blockIdx.x * blockDim.x + threadIdx.x;     // 0 .. B_*H_-1
    int b = idx >> 8;
    int h = idx & (H_ - 1);
    const float* p = enc     + (b * TE_) * H_ + h;
    float*       q = g_ortho + (b * TE_) * H_ + h;
    float s = 0.0f;
#pragma unroll 4
    for (int t = 0; t < TE_; t++) {
        float x = p[t * H_];
        float o = x - __fdividef(x * s, x * x) * x;
        q[t * H_] = o;
        s += x;
    }
}

// ---------------------------------------------------------------------------
// smem-tiled SGEMM:  C[M,256] = A[M,256] @ W[256,256]
// ---------------------------------------------------------------------------
__device__ __forceinline__ void gemm_body(const float* __restrict__ A,
                                          const float* __restrict__ W,
                                          float* __restrict__ C) {
    __shared__ float As[16][65];
    __shared__ float Bs[16][65];
    const int bm = blockIdx.y * 64;
    const int bn = blockIdx.x * 64;
    const int tid = threadIdx.x;
    const int tr = tid >> 4;
    const int tc = tid & 15;

    float acc[4][4];
#pragma unroll
    for (int i = 0; i < 4; i++)
#pragma unroll
        for (int j = 0; j < 4; j++) acc[i][j] = 0.0f;

    for (int k0 = 0; k0 < 256; k0 += 16) {
#pragma unroll
        for (int i = tid; i < 1024; i += 256) {
            int m = i >> 4, kk = i & 15;
            As[kk][m] = A[(bm + m) * 256 + k0 + kk];
        }
#pragma unroll
        for (int i = tid; i < 1024; i += 256) {
            int kk = i >> 6, n = i & 63;
            Bs[kk][n] = W[(k0 + kk) * 256 + bn + n];
        }
        __syncthreads();
#pragma unroll
        for (int kk = 0; kk < 16; kk++) {
            float a[4], bb[4];
#pragma unroll
            for (int i = 0; i < 4; i++) a[i] = As[kk][tr * 4 + i];
#pragma unroll
            for (int j = 0; j < 4; j++) bb[j] = Bs[kk][tc * 4 + j];
#pragma unroll
            for (int i = 0; i < 4; i++)
#pragma unroll
                for (int j = 0; j < 4; j++)
                    acc[i][j] = fmaf(a[i], bb[j], acc[i][j]);
        }
        __syncthreads();
    }
#pragma unroll
    for (int i = 0; i < 4; i++)
#pragma unroll
        for (int j = 0; j < 4; j++)
            C[(bm + tr * 4 + i) * 256 + bn + tc * 4 + j] = acc[i][j];
}

__global__ __launch_bounds__(256) void gemm_was_kernel(const float* __restrict__ Wa) {
    gemm_body(g_ortho, Wa, g_was);
}

__global__ __launch_bounds__(256) void gemm_uah_kernel(const float* __restrict__ dec,
                                                       const float* __restrict__ Ua) {
    gemm_body(dec, Ua, g_uah);
}

// ---------------------------------------------------------------------------
// Kernel 3: fused energy + softmax + context.
// Block = (b, tile of 8 decoder positions), 256 threads = 8 warps,
// warp w owns decoder position d = d0 + w.
// Lane l covers h = {4l..4l+3} and {128+4l..128+4l+3} (two float4 groups).
// Per-e partial sums go through a padded smem transpose-reduce (no SHFL on
// the tanh critical path).
// ---------------------------------------------------------------------------
__global__ __launch_bounds__(256) void attn_kernel(const float* __restrict__ Va,
                                                   float* __restrict__ c_out,
                                                   float* __restrict__ e_out) {
    const int b    = blockIdx.y;
    const int d0   = blockIdx.x * 8;
    const int tid  = threadIdx.x;
    const int warp = tid >> 5;
    const int lane = tid & 31;

    __shared__ float part[8][32][33];   // [warp][e_local][lane], pad 33
    __shared__ float en_s[8][TE_];      // energies per (d_local, e)
    __shared__ float pT_s[TE_][9];      // transposed probs [e][d_local], pad 9

    const int d = d0 + warp;

    // Register preload (float4 groups)
    const float4 v0 = *(const float4*)(Va + 4 * lane);
    const float4 v1 = *(const float4*)(Va + 128 + 4 * lane);
    const float* urow = g_uah + ((b * TD_) + d) * H_;
    const float4 u0 = *(const float4*)(urow + 4 * lane);
    const float4 u1 = *(const float4*)(urow + 128 + 4 * lane);

    const float* wbase = g_was + (b * TE_) * H_;

    // ---- Energies ----
    for (int e0 = 0; e0 < TE_; e0 += 32) {
#pragma unroll 2
        for (int el = 0; el < 32; el++) {
            const float* wr = wbase + (e0 + el) * H_;
            float4 w0 = *(const float4*)(wr + 4 * lane);
            float4 w1 = *(const float4*)(wr + 128 + 4 * lane);
            float t0 = tanh_fast(w0.x + u0.x) * v0.x;
            float t1 = tanh_fast(w0.y + u0.y) * v0.y;
            float t2 = tanh_fast(w0.z + u0.z) * v0.z;
            float t3 = tanh_fast(w0.w + u0.w) * v0.w;
            float t4 = tanh_fast(w1.x + u1.x) * v1.x;
            float t5 = tanh_fast(w1.y + u1.y) * v1.y;
            float t6 = tanh_fast(w1.z + u1.z) * v1.z;
            float t7 = tanh_fast(w1.w + u1.w) * v1.w;
            float s = ((t0 + t1) + (t2 + t3)) + ((t4 + t5) + (t6 + t7));
            part[warp][el][lane] = s;
        }
        __syncwarp();
        // transpose-reduce: lane sums row 'lane' (stride 33 -> conflict-free)
        {
            float s = 0.0f;
#pragma unroll
            for (int j = 0; j < 32; j++) s += part[warp][lane][j];
            en_s[warp][e0 + lane] = s;
        }
        __syncwarp();
    }

    // ---- Softmax over e (warp owns its d row) ----
    {
        float v0s = en_s[warp][lane];
        float v1s = en_s[warp][lane + 32];
        float v2s = en_s[warp][lane + 64];
        float v3s = en_s[warp][lane + 96];
        float m = fmaxf(fmaxf(v0s, v1s), fmaxf(v2s, v3s));
#pragma unroll
        for (int o = 16; o > 0; o >>= 1)
            m = fmaxf(m, __shfl_xor_sync(0xffffffffu, m, o));
        float e0v = __expf(v0s - m), e1v = __expf(v1s - m);
        float e2v = __expf(v2s - m), e3v = __expf(v3s - m);
        float s = e0v + e1v + e2v + e3v;
#pragma unroll
        for (int o = 16; o > 0; o >>= 1)
            s += __shfl_xor_sync(0xffffffffu, s, o);
        float inv = __fdividef(1.0f, s);
        float p0 = e0v * inv, p1 = e1v * inv, p2 = e2v * inv, p3 = e3v * inv;
        pT_s[lane     ][warp] = p0;
        pT_s[lane + 32][warp] = p1;
        pT_s[lane + 64][warp] = p2;
        pT_s[lane + 96][warp] = p3;
        float* eo = e_out + ((b * TD_) + d) * TE_;
        eo[lane]      = p0;
        eo[lane + 32] = p1;
        eo[lane + 64] = p2;
        eo[lane + 96] = p3;
    }
    __syncthreads();

    // ---- Context: c[d][h] = sum_e p[d][e] * ortho[b][e][h]; thread = h ----
    float acc[8];
#pragma unroll
    for (int j = 0; j < 8; j++) acc[j] = 0.0f;
    const float* eb = g_ortho + (b * TE_) * H_ + tid;
#pragma unroll 4
    for (int e = 0; e < TE_; e++) {
        float x = eb[e * H_];
#pragma unroll
        for (int j = 0; j < 8; j++)
            acc[j] = fmaf(pT_s[e][j], x, acc[j]);
    }
#pragma unroll
    for (int j = 0; j < 8; j++)
        c_out[((b * TD_) + (d0 + j)) * H_ + tid] = acc[j];
}

// ---------------------------------------------------------------------------
extern "C" void kernel_launch(void* const* d_in, const int* in_sizes, int n_in,
                              void* d_out, int out_size) {
    const float* enc = (const float*)d_in[0];   // [16,128,256]
    const float* dec = (const float*)d_in[1];   // [16,128,256]
    const float* Wa  = (const float*)d_in[2];   // [256,256]
    const float* Ua  = (const float*)d_in[3];   // [256,256]
    const float* Va  = (const float*)d_in[4];   // [256,1]

    float* out   = (float*)d_out;
    float* c_out = out;                          // [16,128,256]
    float* e_out = out + B_ * TD_ * H_;          // [16,128,128]

    ortho_kernel<<<(B_ * H_) / 256, 256>>>(enc);
    gemm_was_kernel<<<dim3(4, 32), 256>>>(Wa);
    gemm_uah_kernel<<<dim3(4, 32), 256>>>(dec, Ua);
    attn_kernel<<<dim3(TD_ / 8, B_), 256>>>(Va, c_out, e_out);
}

// round 4
// speedup vs baseline: 2.3330x; 1.6679x over previous
#include <cuda_runtime.h>
#include <cuda_bf16.h>

// Problem constants
#define B_   16
#define TE_  128
#define TD_  128
#define H_   256

// Scratch (device globals)
__device__ float g_ortho[B_ * TE_ * H_];   // orthogonalized encoder [B, TE, H]
__device__ float g_was  [B_ * TE_ * H_];   // ortho @ W_a
__device__ float g_uah  [B_ * TD_ * H_];   // dec @ U_a

__device__ __forceinline__ float tanh_fast(float x) {
    float y;
    asm("tanh.approx.f32 %0, %1;" : "=f"(y) : "f"(x));
    return y;
}

// ---------------------------------------------------------------------------
// Kernel 1: Gram-Schmidt-style pass.
// ---------------------------------------------------------------------------
__global__ void ortho_kernel(const float* __restrict__ enc) {
    int idx = blockIdx.x * blockDim.x + threadIdx.x;
    int b = idx >> 8;
    int h = idx & (H_ - 1);
    const float* p = enc     + (b * TE_) * H_ + h;
    float*       q = g_ortho + (b * TE_) * H_ + h;
    float s = 0.0f;
#pragma unroll 4
    for (int t = 0; t < TE_; t++) {
        float x = p[t * H_];
        float o = x - __fdividef(x * s, x * x) * x;
        q[t * H_] = o;
        s += x;
    }
}

// ---------------------------------------------------------------------------
// Fused dual SGEMM: z=0 -> g_was = g_ortho @ Wa ; z=1 -> g_uah = dec @ Ua
// ---------------------------------------------------------------------------
__global__ __launch_bounds__(256) void gemm_both_kernel(const float* __restrict__ dec,
                                                        const float* __restrict__ Wa,
                                                        const float* __restrict__ Ua) {
    const float* A = (blockIdx.z == 0) ? g_ortho : dec;
    const float* W = (blockIdx.z == 0) ? Wa : Ua;
    float*       C = (blockIdx.z == 0) ? g_was : g_uah;

    __shared__ float As[16][65];
    __shared__ float Bs[16][65];
    const int bm = blockIdx.y * 64;
    const int bn = blockIdx.x * 64;
    const int tid = threadIdx.x;
    const int tr = tid >> 4;
    const int tc = tid & 15;

    float acc[4][4];
#pragma unroll
    for (int i = 0; i < 4; i++)
#pragma unroll
        for (int j = 0; j < 4; j++) acc[i][j] = 0.0f;

    for (int k0 = 0; k0 < 256; k0 += 16) {
#pragma unroll
        for (int i = tid; i < 1024; i += 256) {
            int m = i >> 4, kk = i & 15;
            As[kk][m] = A[(bm + m) * 256 + k0 + kk];
        }
#pragma unroll
        for (int i = tid; i < 1024; i += 256) {
            int kk = i >> 6, n = i & 63;
            Bs[kk][n] = W[(k0 + kk) * 256 + bn + n];
        }
        __syncthreads();
#pragma unroll
        for (int kk = 0; kk < 16; kk++) {
            float a[4], bb[4];
#pragma unroll
            for (int i = 0; i < 4; i++) a[i] = As[kk][tr * 4 + i];
#pragma unroll
            for (int j = 0; j < 4; j++) bb[j] = Bs[kk][tc * 4 + j];
#pragma unroll
            for (int i = 0; i < 4; i++)
#pragma unroll
                for (int j = 0; j < 4; j++)
                    acc[i][j] = fmaf(a[i], bb[j], acc[i][j]);
        }
        __syncthreads();
    }
#pragma unroll
    for (int i = 0; i < 4; i++)
#pragma unroll
        for (int j = 0; j < 4; j++)
            C[(bm + tr * 4 + i) * 256 + bn + tc * 4 + j] = acc[i][j];
}

// ---------------------------------------------------------------------------
// Kernel 3: fused energy + softmax + context.
// Block = (b, tile of 8 decoder positions), 512 threads = 16 warps.
// Warp w (w<8) handles d = d0+w, e in [0,64); warp w+8 same d, e in [64,128).
// ---------------------------------------------------------------------------
__global__ __launch_bounds__(512) void attn_kernel(const float* __restrict__ Va,
                                                   float* __restrict__ c_out,
                                                   float* __restrict__ e_out) {
    const int b    = blockIdx.y;
    const int d0   = blockIdx.x * 8;
    const int tid  = threadIdx.x;
    const int warp = tid >> 5;
    const int lane = tid & 31;
    const int wd   = warp & 7;           // which d
    const int eh   = warp >> 3;          // which e-half (0 or 1)

    __shared__ float part[16][16][33];   // [warp][e_local][lane] (33: full lane dim + pad)
    __shared__ float en_s[8][TE_];       // energies [d_local][e]
    __shared__ float pT_s[TE_][9];       // transposed probs [e][d_local]
    __shared__ float cpart[8][256];      // context partials from upper half

    const int d = d0 + wd;

    // Register preload (float4 groups over h)
    const float4 v0 = *(const float4*)(Va + 4 * lane);
    const float4 v1 = *(const float4*)(Va + 128 + 4 * lane);
    const float* urow = g_uah + ((b * TD_) + d) * H_;
    const float4 u0 = *(const float4*)(urow + 4 * lane);
    const float4 u1 = *(const float4*)(urow + 128 + 4 * lane);

    const float* wbase = g_was + (b * TE_) * H_;
    const int ebase = eh * 64;

    // ---- Energies: 64 e per warp, chunks of 16 ----
    for (int c0 = 0; c0 < 64; c0 += 16) {
#pragma unroll 4
        for (int el = 0; el < 16; el++) {
            const float* wr = wbase + (ebase + c0 + el) * H_;
            float4 w0 = *(const float4*)(wr + 4 * lane);
            float4 w1 = *(const float4*)(wr + 128 + 4 * lane);
            float t0 = tanh_fast(w0.x + u0.x) * v0.x;
            float t1 = tanh_fast(w0.y + u0.y) * v0.y;
            float t2 = tanh_fast(w0.z + u0.z) * v0.z;
            float t3 = tanh_fast(w0.w + u0.w) * v0.w;
            float t4 = tanh_fast(w1.x + u1.x) * v1.x;
            float t5 = tanh_fast(w1.y + u1.y) * v1.y;
            float t6 = tanh_fast(w1.z + u1.z) * v1.z;
            float t7 = tanh_fast(w1.w + u1.w) * v1.w;
            float s = ((t0 + t1) + (t2 + t3)) + ((t4 + t5) + (t6 + t7));
            part[warp][el][lane] = s;
        }
        __syncwarp();
        if (lane < 16) {
            float s = 0.0f;
#pragma unroll
            for (int j = 0; j < 32; j++) s += part[warp][lane][j];
            en_s[wd][ebase + c0 + lane] = s;
        }
        __syncwarp();
    }
    __syncthreads();

    // ---- Softmax over e (warps 0-7, one d each) ----
    if (warp < 8) {
        float v0s = en_s[wd][lane];
        float v1s = en_s[wd][lane + 32];
        float v2s = en_s[wd][lane + 64];
        float v3s = en_s[wd][lane + 96];
        float m = fmaxf(fmaxf(v0s, v1s), fmaxf(v2s, v3s));
#pragma unroll
        for (int o = 16; o > 0; o >>= 1)
            m = fmaxf(m, __shfl_xor_sync(0xffffffffu, m, o));
        float e0v = __expf(v0s - m), e1v = __expf(v1s - m);
        float e2v = __expf(v2s - m), e3v = __expf(v3s - m);
        float s = e0v + e1v + e2v + e3v;
#pragma unroll
        for (int o = 16; o > 0; o >>= 1)
            s += __shfl_xor_sync(0xffffffffu, s, o);
        float inv = __fdividef(1.0f, s);
        float p0 = e0v * inv, p1 = e1v * inv, p2 = e2v * inv, p3 = e3v * inv;
        pT_s[lane     ][wd] = p0;
        pT_s[lane + 32][wd] = p1;
        pT_s[lane + 64][wd] = p2;
        pT_s[lane + 96][wd] = p3;
        float* eo = e_out + ((b * TD_) + d) * TE_;
        eo[lane]      = p0;
        eo[lane + 32] = p1;
        eo[lane + 64] = p2;
        eo[lane + 96] = p3;
    }
    __syncthreads();

    // ---- Context: c[d][h] = sum_e p[d][e] * ortho[b][e][h] ----
    // Lower half (tid<256): e 0..63. Upper half: e 64..127 -> cpart.
    {
        const int h = tid & 255;
        const int half = tid >> 8;
        float acc[8];
#pragma unroll
        for (int j = 0; j < 8; j++) acc[j] = 0.0f;
        const float* eb = g_ortho + (b * TE_ + half * 64) * H_ + h;
        const float (*pp)[9] = &pT_s[half * 64];
#pragma unroll 4
        for (int e = 0; e < 64; e++) {
            float x = eb[e * H_];
#pragma unroll
            for (int j = 0; j < 8; j++)
                acc[j] = fmaf(pp[e][j], x, acc[j]);
        }
        if (half == 1) {
#pragma unroll
            for (int j = 0; j < 8; j++) cpart[j][h] = acc[j];
        }
        __syncthreads();
        if (half == 0) {
#pragma unroll
            for (int j = 0; j < 8; j++)
                c_out[((b * TD_) + (d0 + j)) * H_ + h] = acc[j] + cpart[j][h];
        }
    }
}

// ---------------------------------------------------------------------------
extern "C" void kernel_launch(void* const* d_in, const int* in_sizes, int n_in,
                              void* d_out, int out_size) {
    const float* enc = (const float*)d_in[0];   // [16,128,256]
    const float* dec = (const float*)d_in[1];   // [16,128,256]
    const float* Wa  = (const float*)d_in[2];   // [256,256]
    const float* Ua  = (const float*)d_in[3];   // [256,256]
    const float* Va  = (const float*)d_in[4];   // [256,1]

    float* out   = (float*)d_out;
    float* c_out = out;                          // [16,128,256]
    float* e_out = out + B_ * TD_ * H_;          // [16,128,128]

    ortho_kernel<<<(B_ * H_) / 256, 256>>>(enc);
    gemm_both_kernel<<<dim3(4, 32, 2), 256>>>(dec, Wa, Ua);
    attn_kernel<<<dim3(TD_ / 8, B_), 512>>>(Va, c_out, e_out);
}

// round 5
// speedup vs baseline: 2.4789x; 1.0625x over previous
#include <cuda_runtime.h>
#include <cuda_bf16.h>

// Problem constants
#define B_   16
#define TE_  128
#define TD_  128
#define H_   256

// Scratch (device globals)
__device__ float g_ortho[B_ * TE_ * H_];   // orthogonalized encoder [B, TE, H]
__device__ float g_was  [B_ * TE_ * H_];   // ortho @ W_a
__device__ float g_uah  [B_ * TD_ * H_];   // dec @ U_a

__device__ __forceinline__ float tanh_fast(float x) {
    float y;
    asm("tanh.approx.f32 %0, %1;" : "=f"(y) : "f"(x));
    return y;
}

// ---------------------------------------------------------------------------
// Kernel 1: Gram-Schmidt-style pass, T-chunked for parallelism.
// Block = (chunk of 8 timesteps, b); 256 threads over h.
// Each thread recomputes its prefix sum (coalesced, high-MLP) then runs the
// 8-step serial tail for its chunk.
// ---------------------------------------------------------------------------
#define OCHUNK 8
__global__ __launch_bounds__(256) void ortho_kernel(const float* __restrict__ enc) {
    const int b  = blockIdx.y;
    const int t0 = blockIdx.x * OCHUNK;
    const int h  = threadIdx.x;
    const float* p = enc + (b * TE_) * H_ + h;

    // Prefix sum over t < t0 (independent loads, 4-way tree accumulate)
    float s0 = 0.f, s1 = 0.f, s2 = 0.f, s3 = 0.f;
    int t = 0;
    for (; t + 8 <= t0; t += 8) {
        s0 += p[(t + 0) * H_];
        s1 += p[(t + 1) * H_];
        s2 += p[(t + 2) * H_];
        s3 += p[(t + 3) * H_];
        s0 += p[(t + 4) * H_];
        s1 += p[(t + 5) * H_];
        s2 += p[(t + 6) * H_];
        s3 += p[(t + 7) * H_];
    }
    float s = (s0 + s1) + (s2 + s3);

    // Serial tail: 8 timesteps of this chunk
    float* q = g_ortho + (b * TE_) * H_ + h;
    float xs[OCHUNK];
#pragma unroll
    for (int j = 0; j < OCHUNK; j++) xs[j] = p[(t0 + j) * H_];
#pragma unroll
    for (int j = 0; j < OCHUNK; j++) {
        float x = xs[j];
        q[(t0 + j) * H_] = x - __fdividef(x * s, x * x) * x;
        s += x;
    }
}

// ---------------------------------------------------------------------------
// Fused dual SGEMM: z=0 -> g_was = g_ortho @ Wa ; z=1 -> g_uah = dec @ Ua
// ---------------------------------------------------------------------------
__global__ __launch_bounds__(256) void gemm_both_kernel(const float* __restrict__ dec,
                                                        const float* __restrict__ Wa,
                                                        const float* __restrict__ Ua) {
    const float* A = (blockIdx.z == 0) ? g_ortho : dec;
    const float* W = (blockIdx.z == 0) ? Wa : Ua;
    float*       C = (blockIdx.z == 0) ? g_was : g_uah;

    __shared__ float As[16][65];
    __shared__ float Bs[16][65];
    const int bm = blockIdx.y * 64;
    const int bn = blockIdx.x * 64;
    const int tid = threadIdx.x;
    const int tr = tid >> 4;
    const int tc = tid & 15;

    float acc[4][4];
#pragma unroll
    for (int i = 0; i < 4; i++)
#pragma unroll
        for (int j = 0; j < 4; j++) acc[i][j] = 0.0f;

    for (int k0 = 0; k0 < 256; k0 += 16) {
#pragma unroll
        for (int i = tid; i < 1024; i += 256) {
            int m = i >> 4, kk = i & 15;
            As[kk][m] = A[(bm + m) * 256 + k0 + kk];
        }
#pragma unroll
        for (int i = tid; i < 1024; i += 256) {
            int kk = i >> 6, n = i & 63;
            Bs[kk][n] = W[(k0 + kk) * 256 + bn + n];
        }
        __syncthreads();
#pragma unroll
        for (int kk = 0; kk < 16; kk++) {
            float a[4], bb[4];
#pragma unroll
            for (int i = 0; i < 4; i++) a[i] = As[kk][tr * 4 + i];
#pragma unroll
            for (int j = 0; j < 4; j++) bb[j] = Bs[kk][tc * 4 + j];
#pragma unroll
            for (int i = 0; i < 4; i++)
#pragma unroll
                for (int j = 0; j < 4; j++)
                    acc[i][j] = fmaf(a[i], bb[j], acc[i][j]);
        }
        __syncthreads();
    }
#pragma unroll
    for (int i = 0; i < 4; i++)
#pragma unroll
        for (int j = 0; j < 4; j++)
            C[(bm + tr * 4 + i) * 256 + bn + tc * 4 + j] = acc[i][j];
}

// ---------------------------------------------------------------------------
// Kernel 3: fused energy + softmax + context.
// Block = (b, tile of 8 decoder positions), 512 threads = 16 warps.
// Warp w (w<8) handles d = d0+w, e in [0,64); warp w+8 same d, e in [64,128).
// ---------------------------------------------------------------------------
__global__ __launch_bounds__(512) void attn_kernel(const float* __restrict__ Va,
                                                   float* __restrict__ c_out,
                                                   float* __restrict__ e_out) {
    const int b    = blockIdx.y;
    const int d0   = blockIdx.x * 8;
    const int tid  = threadIdx.x;
    const int warp = tid >> 5;
    const int lane = tid & 31;
    const int wd   = warp & 7;           // which d
    const int eh   = warp >> 3;          // which e-half (0 or 1)

    __shared__ float part[16][16][33];   // [warp][e_local][lane]
    __shared__ float en_s[8][TE_];       // energies [d_local][e]
    __shared__ float pT_s[TE_][9];       // transposed probs [e][d_local]
    __shared__ float cpart[8][256];      // context partials from upper half

    const int d = d0 + wd;

    const float4 v0 = *(const float4*)(Va + 4 * lane);
    const float4 v1 = *(const float4*)(Va + 128 + 4 * lane);
    const float* urow = g_uah + ((b * TD_) + d) * H_;
    const float4 u0 = *(const float4*)(urow + 4 * lane);
    const float4 u1 = *(const float4*)(urow + 128 + 4 * lane);

    const float* wbase = g_was + (b * TE_) * H_;
    const int ebase = eh * 64;

    // ---- Energies: 64 e per warp, chunks of 16 ----
    for (int c0 = 0; c0 < 64; c0 += 16) {
#pragma unroll 4
        for (int el = 0; el < 16; el++) {
            const float* wr = wbase + (ebase + c0 + el) * H_;
            float4 w0 = *(const float4*)(wr + 4 * lane);
            float4 w1 = *(const float4*)(wr + 128 + 4 * lane);
            float t0 = tanh_fast(w0.x + u0.x) * v0.x;
            float t1 = tanh_fast(w0.y + u0.y) * v0.y;
            float t2 = tanh_fast(w0.z + u0.z) * v0.z;
            float t3 = tanh_fast(w0.w + u0.w) * v0.w;
            float t4 = tanh_fast(w1.x + u1.x) * v1.x;
            float t5 = tanh_fast(w1.y + u1.y) * v1.y;
            float t6 = tanh_fast(w1.z + u1.z) * v1.z;
            float t7 = tanh_fast(w1.w + u1.w) * v1.w;
            float s = ((t0 + t1) + (t2 + t3)) + ((t4 + t5) + (t6 + t7));
            part[warp][el][lane] = s;
        }
        __syncwarp();
        if (lane < 16) {
            float s = 0.0f;
#pragma unroll
            for (int j = 0; j < 32; j++) s += part[warp][lane][j];
            en_s[wd][ebase + c0 + lane] = s;
        }
        __syncwarp();
    }
    __syncthreads();

    // ---- Softmax over e (warps 0-7, one d each) ----
    if (warp < 8) {
        float v0s = en_s[wd][lane];
        float v1s = en_s[wd][lane + 32];
        float v2s = en_s[wd][lane + 64];
        float v3s = en_s[wd][lane + 96];
        float m = fmaxf(fmaxf(v0s, v1s), fmaxf(v2s, v3s));
#pragma unroll
        for (int o = 16; o > 0; o >>= 1)
            m = fmaxf(m, __shfl_xor_sync(0xffffffffu, m, o));
        float e0v = __expf(v0s - m), e1v = __expf(v1s - m);
        float e2v = __expf(v2s - m), e3v = __expf(v3s - m);
        float s = e0v + e1v + e2v + e3v;
#pragma unroll
        for (int o = 16; o > 0; o >>= 1)
            s += __shfl_xor_sync(0xffffffffu, s, o);
        float inv = __fdividef(1.0f, s);
        float p0 = e0v * inv, p1 = e1v * inv, p2 = e2v * inv, p3 = e3v * inv;
        pT_s[lane     ][wd] = p0;
        pT_s[lane + 32][wd] = p1;
        pT_s[lane + 64][wd] = p2;
        pT_s[lane + 96][wd] = p3;
        float* eo = e_out + ((b * TD_) + d) * TE_;
        eo[lane]      = p0;
        eo[lane + 32] = p1;
        eo[lane + 64] = p2;
        eo[lane + 96] = p3;
    }
    __syncthreads();

    // ---- Context: c[d][h] = sum_e p[d][e] * ortho[b][e][h] ----
    {
        const int h = tid & 255;
        const int half = tid >> 8;
        float acc[8];
#pragma unroll
        for (int j = 0; j < 8; j++) acc[j] = 0.0f;
        const float* eb = g_ortho + (b * TE_ + half * 64) * H_ + h;
        const float (*pp)[9] = &pT_s[half * 64];
#pragma unroll 4
        for (int e = 0; e < 64; e++) {
            float x = eb[e * H_];
#pragma unroll
            for (int j = 0; j < 8; j++)
                acc[j] = fmaf(pp[e][j], x, acc[j]);
        }
        if (half == 1) {
#pragma unroll
            for (int j = 0; j < 8; j++) cpart[j][h] = acc[j];
        }
        __syncthreads();
        if (half == 0) {
#pragma unroll
            for (int j = 0; j < 8; j++)
                c_out[((b * TD_) + (d0 + j)) * H_ + h] = acc[j] + cpart[j][h];
        }
    }
}

// ---------------------------------------------------------------------------
extern "C" void kernel_launch(void* const* d_in, const int* in_sizes, int n_in,
                              void* d_out, int out_size) {
    const float* enc = (const float*)d_in[0];   // [16,128,256]
    const float* dec = (const float*)d_in[1];   // [16,128,256]
    const float* Wa  = (const float*)d_in[2];   // [256,256]
    const float* Ua  = (const float*)d_in[3];   // [256,256]
    const float* Va  = (const float*)d_in[4];   // [256,1]

    float* out   = (float*)d_out;
    float* c_out = out;                          // [16,128,256]
    float* e_out = out + B_ * TD_ * H_;          // [16,128,128]

    ortho_kernel<<<dim3(TE_ / OCHUNK, B_), 256>>>(enc);
    gemm_both_kernel<<<dim3(4, 32, 2), 256>>>(dec, Wa, Ua);
    attn_kernel<<<dim3(TD_ / 8, B_), 512>>>(Va, c_out, e_out);
}

// round 6
// speedup vs baseline: 2.5494x; 1.0284x over previous
#include <cuda_runtime.h>
#include <cuda_bf16.h>

// Problem constants
#define B_   16
#define TE_  128
#define TD_  128
#define H_   256

// Scratch (device globals)
__device__ float g_ortho[B_ * TE_ * H_];   // enc - cumsum_excl(enc)
__device__ float g_was  [B_ * TE_ * H_];   // (enc@Wa) then in-place scanned
__device__ float g_uah  [B_ * TD_ * H_];   // dec @ U_a

__device__ __forceinline__ float tanh_fast(float x) {
    float y;
    asm("tanh.approx.f32 %0, %1;" : "=f"(y) : "f"(x));
    return y;
}

// ---------------------------------------------------------------------------
// Scan block: out[b, t, hg*32+hl] = in[b,t,..] - sum_{t'<t} in[b,t',..]
// 256 threads, smem-transposed tile, warp-shuffle scan over T=128.
// Each warp scans 4 h-columns; lane l holds t = 4l..4l+3.
// ---------------------------------------------------------------------------
__device__ __forceinline__ void scan_block(const float* __restrict__ in,
                                           float* __restrict__ out,
                                           int b, int hg, float* sm /*[128*33]*/) {
    const int tid  = threadIdx.x;
    const int warp = tid >> 5;
    const int lane = tid & 31;

    const float* base = in + (b * TE_) * H_ + hg * 32;
#pragma unroll
    for (int k = 0; k < 16; k++) {
        int idx = tid + k * 256;          // 0..4095
        int t = idx >> 5, hl = idx & 31;
        sm[t * 33 + hl] = base[t * H_ + hl];
    }
    __syncthreads();

#pragma unroll
    for (int c = 0; c < 4; c++) {
        int h = warp * 4 + c;
        float a0 = sm[(4 * lane + 0) * 33 + h];
        float a1 = sm[(4 * lane + 1) * 33 + h];
        float a2 = sm[(4 * lane + 2) * 33 + h];
        float a3 = sm[(4 * lane + 3) * 33 + h];
        float L = (a0 + a1) + (a2 + a3);
        float sc = L;
#pragma unroll
        for (int o = 1; o < 32; o <<= 1) {
            float v = __shfl_up_sync(0xffffffffu, sc, o);
            if (lane >= o) sc += v;
        }
        float p = sc - L;                 // exclusive prefix of lane sums
        float o0 = a0 - p; p += a0;
        float o1 = a1 - p; p += a1;
        float o2 = a2 - p; p += a2;
        float o3 = a3 - p;
        sm[(4 * lane + 0) * 33 + h] = o0;
        sm[(4 * lane + 1) * 33 + h] = o1;
        sm[(4 * lane + 2) * 33 + h] = o2;
        sm[(4 * lane + 3) * 33 + h] = o3;
    }
    __syncthreads();

    float* obase = out + (b * TE_) * H_ + hg * 32;
#pragma unroll
    for (int k = 0; k < 16; k++) {
        int idx = tid + k * 256;
        int t = idx >> 5, hl = idx & 31;
        obase[t * H_ + hl] = sm[t * 33 + hl];
    }
}

// ---------------------------------------------------------------------------
// K1: z=0 -> g_was = enc @ Wa (raw, pre-scan); z=1 -> g_uah = dec @ Ua;
//     z=2 -> g_ortho = enc - cumsum_excl(enc)  (128 scan blocks, concurrent)
// ---------------------------------------------------------------------------
__global__ __launch_bounds__(256) void k1_kernel(const float* __restrict__ enc,
                                                 const float* __restrict__ dec,
                                                 const float* __restrict__ Wa,
                                                 const float* __restrict__ Ua) {
    __shared__ float sm[128 * 33];        // scan tile / gemm tiles (aliased)

    if (blockIdx.z == 2) {
        int lin = blockIdx.y * 4 + blockIdx.x;   // 0..127
        scan_block(enc, g_ortho, lin >> 3, lin & 7, sm);
        return;
    }

    const float* A = (blockIdx.z == 0) ? enc : dec;
    const float* W = (blockIdx.z == 0) ? Wa : Ua;
    float*       C = (blockIdx.z == 0) ? g_was : g_uah;

    float (*As)[65] = (float (*)[65])sm;
    float (*Bs)[65] = (float (*)[65])(sm + 16 * 65);

    const int bm = blockIdx.y * 64;
    const int bn = blockIdx.x * 64;
    const int tid = threadIdx.x;
    const int tr = tid >> 4;
    const int tc = tid & 15;

    float acc[4][4];
#pragma unroll
    for (int i = 0; i < 4; i++)
#pragma unroll
        for (int j = 0; j < 4; j++) acc[i][j] = 0.0f;

    for (int k0 = 0; k0 < 256; k0 += 16) {
#pragma unroll
        for (int i = tid; i < 1024; i += 256) {
            int m = i >> 4, kk = i & 15;
            As[kk][m] = A[(bm + m) * 256 + k0 + kk];
        }
#pragma unroll
        for (int i = tid; i < 1024; i += 256) {
            int kk = i >> 6, n = i & 63;
            Bs[kk][n] = W[(k0 + kk) * 256 + bn + n];
        }
        __syncthreads();
#pragma unroll
        for (int kk = 0; kk < 16; kk++) {
            float a[4], bb[4];
#pragma unroll
            for (int i = 0; i < 4; i++) a[i] = As[kk][tr * 4 + i];
#pragma unroll
            for (int j = 0; j < 4; j++) bb[j] = Bs[kk][tc * 4 + j];
#pragma unroll
            for (int i = 0; i < 4; i++)
#pragma unroll
                for (int j = 0; j < 4; j++)
                    acc[i][j] = fmaf(a[i], bb[j], acc[i][j]);
        }
        __syncthreads();
    }
#pragma unroll
    for (int i = 0; i < 4; i++)
#pragma unroll
        for (int j = 0; j < 4; j++)
            C[(bm + tr * 4 + i) * 256 + bn + tc * 4 + j] = acc[i][j];
}

// ---------------------------------------------------------------------------
// K2: in-place scan of g_was:  was = Y - cumsum_excl(Y)   (linearity of @Wa)
// ---------------------------------------------------------------------------
__global__ __launch_bounds__(256) void k2_kernel() {
    __shared__ float sm[128 * 33];
    int lin = blockIdx.x;                 // 0..127
    scan_block(g_was, g_was, lin >> 3, lin & 7, sm);
}

// ---------------------------------------------------------------------------
// K3: fused energy + softmax + context. (unchanged from R4)
// ---------------------------------------------------------------------------
__global__ __launch_bounds__(512) void attn_kernel(const float* __restrict__ Va,
                                                   float* __restrict__ c_out,
                                                   float* __restrict__ e_out) {
    const int b    = blockIdx.y;
    const int d0   = blockIdx.x * 8;
    const int tid  = threadIdx.x;
    const int warp = tid >> 5;
    const int lane = tid & 31;
    const int wd   = warp & 7;
    const int eh   = warp >> 3;

    __shared__ float part[16][16][33];
    __shared__ float en_s[8][TE_];
    __shared__ float pT_s[TE_][9];
    __shared__ float cpart[8][256];

    const int d = d0 + wd;

    const float4 v0 = *(const float4*)(Va + 4 * lane);
    const float4 v1 = *(const float4*)(Va + 128 + 4 * lane);
    const float* urow = g_uah + ((b * TD_) + d) * H_;
    const float4 u0 = *(const float4*)(urow + 4 * lane);
    const float4 u1 = *(const float4*)(urow + 128 + 4 * lane);

    const float* wbase = g_was + (b * TE_) * H_;
    const int ebase = eh * 64;

    for (int c0 = 0; c0 < 64; c0 += 16) {
#pragma unroll 4
        for (int el = 0; el < 16; el++) {
            const float* wr = wbase + (ebase + c0 + el) * H_;
            float4 w0 = *(const float4*)(wr + 4 * lane);
            float4 w1 = *(const float4*)(wr + 128 + 4 * lane);
            float t0 = tanh_fast(w0.x + u0.x) * v0.x;
            float t1 = tanh_fast(w0.y + u0.y) * v0.y;
            float t2 = tanh_fast(w0.z + u0.z) * v0.z;
            float t3 = tanh_fast(w0.w + u0.w) * v0.w;
            float t4 = tanh_fast(w1.x + u1.x) * v1.x;
            float t5 = tanh_fast(w1.y + u1.y) * v1.y;
            float t6 = tanh_fast(w1.z + u1.z) * v1.z;
            float t7 = tanh_fast(w1.w + u1.w) * v1.w;
            float s = ((t0 + t1) + (t2 + t3)) + ((t4 + t5) + (t6 + t7));
            part[warp][el][lane] = s;
        }
        __syncwarp();
        if (lane < 16) {
            float s = 0.0f;
#pragma unroll
            for (int j = 0; j < 32; j++) s += part[warp][lane][j];
            en_s[wd][ebase + c0 + lane] = s;
        }
        __syncwarp();
    }
    __syncthreads();

    if (warp < 8) {
        float v0s = en_s[wd][lane];
        float v1s = en_s[wd][lane + 32];
        float v2s = en_s[wd][lane + 64];
        float v3s = en_s[wd][lane + 96];
        float m = fmaxf(fmaxf(v0s, v1s), fmaxf(v2s, v3s));
#pragma unroll
        for (int o = 16; o > 0; o >>= 1)
            m = fmaxf(m, __shfl_xor_sync(0xffffffffu, m, o));
        float e0v = __expf(v0s - m), e1v = __expf(v1s - m);
        float e2v = __expf(v2s - m), e3v = __expf(v3s - m);
        float s = e0v + e1v + e2v + e3v;
#pragma unroll
        for (int o = 16; o > 0; o >>= 1)
            s += __shfl_xor_sync(0xffffffffu, s, o);
        float inv = __fdividef(1.0f, s);
        float p0 = e0v * inv, p1 = e1v * inv, p2 = e2v * inv, p3 = e3v * inv;
        pT_s[lane     ][wd] = p0;
        pT_s[lane + 32][wd] = p1;
        pT_s[lane + 64][wd] = p2;
        pT_s[lane + 96][wd] = p3;
        float* eo = e_out + ((b * TD_) + d) * TE_;
        eo[lane]      = p0;
        eo[lane + 32] = p1;
        eo[lane + 64] = p2;
        eo[lane + 96] = p3;
    }
    __syncthreads();

    {
        const int h = tid & 255;
        const int half = tid >> 8;
        float acc[8];
#pragma unroll
        for (int j = 0; j < 8; j++) acc[j] = 0.0f;
        const float* eb = g_ortho + (b * TE_ + half * 64) * H_ + h;
        const float (*pp)[9] = &pT_s[half * 64];
#pragma unroll 4
        for (int e = 0; e < 64; e++) {
            float x = eb[e * H_];
#pragma unroll
            for (int j = 0; j < 8; j++)
                acc[j] = fmaf(pp[e][j], x, acc[j]);
        }
        if (half == 1) {
#pragma unroll
            for (int j = 0; j < 8; j++) cpart[j][h] = acc[j];
        }
        __syncthreads();
        if (half == 0) {
#pragma unroll
            for (int j = 0; j < 8; j++)
                c_out[((b * TD_) + (d0 + j)) * H_ + h] = acc[j] + cpart[j][h];
        }
    }
}

// ---------------------------------------------------------------------------
extern "C" void kernel_launch(void* const* d_in, const int* in_sizes, int n_in,
                              void* d_out, int out_size) {
    const float* enc = (const float*)d_in[0];   // [16,128,256]
    const float* dec = (const float*)d_in[1];   // [16,128,256]
    const float* Wa  = (const float*)d_in[2];   // [256,256]
    const float* Ua  = (const float*)d_in[3];   // [256,256]
    const float* Va  = (const float*)d_in[4];   // [256,1]

    float* out   = (float*)d_out;
    float* c_out = out;                          // [16,128,256]
    float* e_out = out + B_ * TD_ * H_;          // [16,128,128]

    k1_kernel<<<dim3(4, 32, 3), 256>>>(enc, dec, Wa, Ua);
    k2_kernel<<<128, 256>>>();
    attn_kernel<<<dim3(TD_ / 8, B_), 512>>>(Va, c_out, e_out);
}

// round 7
// speedup vs baseline: 2.8301x; 1.1101x over previous
#include <cuda_runtime.h>
#include <cuda_bf16.h>

// Problem constants
#define B_   16
#define TE_  128
#define TD_  128
#define H_   256

// Scratch (device globals)
__device__ float g_ortho[B_ * TE_ * H_];   // enc - cumsum_excl(enc)
__device__ float g_was  [B_ * TE_ * H_];   // (enc@Wa) then in-place scanned
__device__ float g_uah  [B_ * TD_ * H_];   // dec @ U_a

__device__ __forceinline__ float tanh_fast(float x) {
    float y;
    asm("tanh.approx.f32 %0, %1;" : "=f"(y) : "f"(x));
    return y;
}

// ---------------------------------------------------------------------------
// Scan block: out[b, t, hg*32+hl] = in[b,t,..] - sum_{t'<t} in[b,t',..]
// ---------------------------------------------------------------------------
__device__ __forceinline__ void scan_block(const float* __restrict__ in,
                                           float* __restrict__ out,
                                           int b, int hg, float* sm /*[128*33]*/) {
    const int tid  = threadIdx.x;
    const int warp = tid >> 5;
    const int lane = tid & 31;

    const float* base = in + (b * TE_) * H_ + hg * 32;
#pragma unroll
    for (int k = 0; k < 16; k++) {
        int idx = tid + k * 256;
        int t = idx >> 5, hl = idx & 31;
        sm[t * 33 + hl] = base[t * H_ + hl];
    }
    __syncthreads();

#pragma unroll
    for (int c = 0; c < 4; c++) {
        int h = warp * 4 + c;
        float a0 = sm[(4 * lane + 0) * 33 + h];
        float a1 = sm[(4 * lane + 1) * 33 + h];
        float a2 = sm[(4 * lane + 2) * 33 + h];
        float a3 = sm[(4 * lane + 3) * 33 + h];
        float L = (a0 + a1) + (a2 + a3);
        float sc = L;
#pragma unroll
        for (int o = 1; o < 32; o <<= 1) {
            float v = __shfl_up_sync(0xffffffffu, sc, o);
            if (lane >= o) sc += v;
        }
        float p = sc - L;
        float o0 = a0 - p; p += a0;
        float o1 = a1 - p; p += a1;
        float o2 = a2 - p; p += a2;
        float o3 = a3 - p;
        sm[(4 * lane + 0) * 33 + h] = o0;
        sm[(4 * lane + 1) * 33 + h] = o1;
        sm[(4 * lane + 2) * 33 + h] = o2;
        sm[(4 * lane + 3) * 33 + h] = o3;
    }
    __syncthreads();

    float* obase = out + (b * TE_) * H_ + hg * 32;
#pragma unroll
    for (int k = 0; k < 16; k++) {
        int idx = tid + k * 256;
        int t = idx >> 5, hl = idx & 31;
        obase[t * H_ + hl] = sm[t * 33 + hl];
    }
}

// ---------------------------------------------------------------------------
// K1: z=0 -> g_was = enc @ Wa ; z=1 -> g_uah = dec @ Ua ;
//     z=2 -> g_ortho = enc - cumsum_excl(enc)  (concurrent scan blocks)
// GEMM: 64x64 tile, 256 threads, 4x4 microtile, fully vectorized smem path.
// ---------------------------------------------------------------------------
__global__ __launch_bounds__(256) void k1_kernel(const float* __restrict__ enc,
                                                 const float* __restrict__ dec,
                                                 const float* __restrict__ Wa,
                                                 const float* __restrict__ Ua) {
    __shared__ __align__(16) float sm[128 * 33];  // 16.9KB (scan) / gemm tiles

    if (blockIdx.z == 2) {
        int lin = blockIdx.y * 4 + blockIdx.x;    // 0..127
        scan_block(enc, g_ortho, lin >> 3, lin & 7, sm);
        return;
    }

    const float* A = (blockIdx.z == 0) ? enc : dec;
    const float* W = (blockIdx.z == 0) ? Wa : Ua;
    float*       C = (blockIdx.z == 0) ? g_was : g_uah;

    // Tiles padded to stride 68 (16B-aligned rows, conflict-benign)
    float (*As)[68] = (float (*)[68])sm;              // [16][68]
    float (*Bs)[68] = (float (*)[68])(sm + 16 * 68);  // [16][68]

    const int bm = blockIdx.y * 64;
    const int bn = blockIdx.x * 64;
    const int tid = threadIdx.x;
    const int tr = tid >> 4;       // 0..15
    const int tc = tid & 15;       // 0..15

    // Per-thread load coordinates
    const int lam = tid >> 2;      // A: m row 0..63
    const int laq = tid & 3;       // A: k-quad 0..3
    const int lbk = tid >> 4;      // B: k row 0..15
    const int lbq = tid & 15;      // B: n-quad 0..15

    float acc[4][4];
#pragma unroll
    for (int i = 0; i < 4; i++)
#pragma unroll
        for (int j = 0; j < 4; j++) acc[i][j] = 0.0f;

    for (int k0 = 0; k0 < 256; k0 += 16) {
        // A tile: LDG.128 along k, transpose via 4 scalar STS
        float4 av = *(const float4*)&A[(bm + lam) * 256 + k0 + laq * 4];
        As[laq * 4 + 0][lam] = av.x;
        As[laq * 4 + 1][lam] = av.y;
        As[laq * 4 + 2][lam] = av.z;
        As[laq * 4 + 3][lam] = av.w;
        // B tile: LDG.128 + STS.128 straight through
        *(float4*)&Bs[lbk][lbq * 4] =
            *(const float4*)&W[(k0 + lbk) * 256 + bn + lbq * 4];
        __syncthreads();

#pragma unroll
        for (int kk = 0; kk < 16; kk++) {
            float4 a4 = *(const float4*)&As[kk][tr * 4];
            float4 b4 = *(const float4*)&Bs[kk][tc * 4];
            acc[0][0] = fmaf(a4.x, b4.x, acc[0][0]);
            acc[0][1] = fmaf(a4.x, b4.y, acc[0][1]);
            acc[0][2] = fmaf(a4.x, b4.z, acc[0][2]);
            acc[0][3] = fmaf(a4.x, b4.w, acc[0][3]);
            acc[1][0] = fmaf(a4.y, b4.x, acc[1][0]);
            acc[1][1] = fmaf(a4.y, b4.y, acc[1][1]);
            acc[1][2] = fmaf(a4.y, b4.z, acc[1][2]);
            acc[1][3] = fmaf(a4.y, b4.w, acc[1][3]);
            acc[2][0] = fmaf(a4.z, b4.x, acc[2][0]);
            acc[2][1] = fmaf(a4.z, b4.y, acc[2][1]);
            acc[2][2] = fmaf(a4.z, b4.z, acc[2][2]);
            acc[2][3] = fmaf(a4.z, b4.w, acc[2][3]);
            acc[3][0] = fmaf(a4.w, b4.x, acc[3][0]);
            acc[3][1] = fmaf(a4.w, b4.y, acc[3][1]);
            acc[3][2] = fmaf(a4.w, b4.z, acc[3][2]);
            acc[3][3] = fmaf(a4.w, b4.w, acc[3][3]);
        }
        __syncthreads();
    }

    // Vectorized store: each thread owns rows bm+tr*4.., cols bn+tc*4..
#pragma unroll
    for (int i = 0; i < 4; i++) {
        float4 o;
        o.x = acc[i][0]; o.y = acc[i][1]; o.z = acc[i][2]; o.w = acc[i][3];
        *(float4*)&C[(bm + tr * 4 + i) * 256 + bn + tc * 4] = o;
    }
}

// ---------------------------------------------------------------------------
// K2: in-place scan of g_was:  was = Y - cumsum_excl(Y)
// ---------------------------------------------------------------------------
__global__ __launch_bounds__(256) void k2_kernel() {
    __shared__ float sm[128 * 33];
    int lin = blockIdx.x;
    scan_block(g_was, g_was, lin >> 3, lin & 7, sm);
}

// ---------------------------------------------------------------------------
// K3: fused energy + softmax + context.
// ---------------------------------------------------------------------------
__global__ __launch_bounds__(512) void attn_kernel(const float* __restrict__ Va,
                                                   float* __restrict__ c_out,
                                                   float* __restrict__ e_out) {
    const int b    = blockIdx.y;
    const int d0   = blockIdx.x * 8;
    const int tid  = threadIdx.x;
    const int warp = tid >> 5;
    const int lane = tid & 31;
    const int wd   = warp & 7;
    const int eh   = warp >> 3;

    __shared__ float part[16][16][33];
    __shared__ float en_s[8][TE_];
    __shared__ float pT_s[TE_][9];
    __shared__ float cpart[8][256];

    const int d = d0 + wd;

    const float4 v0 = *(const float4*)(Va + 4 * lane);
    const float4 v1 = *(const float4*)(Va + 128 + 4 * lane);
    const float* urow = g_uah + ((b * TD_) + d) * H_;
    const float4 u0 = *(const float4*)(urow + 4 * lane);
    const float4 u1 = *(const float4*)(urow + 128 + 4 * lane);

    const float* wbase = g_was + (b * TE_) * H_;
    const int ebase = eh * 64;

    for (int c0 = 0; c0 < 64; c0 += 16) {
#pragma unroll 4
        for (int el = 0; el < 16; el++) {
            const float* wr = wbase + (ebase + c0 + el) * H_;
            float4 w0 = *(const float4*)(wr + 4 * lane);
            float4 w1 = *(const float4*)(wr + 128 + 4 * lane);
            float t0 = tanh_fast(w0.x + u0.x) * v0.x;
            float t1 = tanh_fast(w0.y + u0.y) * v0.y;
            float t2 = tanh_fast(w0.z + u0.z) * v0.z;
            float t3 = tanh_fast(w0.w + u0.w) * v0.w;
            float t4 = tanh_fast(w1.x + u1.x) * v1.x;
            float t5 = tanh_fast(w1.y + u1.y) * v1.y;
            float t6 = tanh_fast(w1.z + u1.z) * v1.z;
            float t7 = tanh_fast(w1.w + u1.w) * v1.w;
            float s = ((t0 + t1) + (t2 + t3)) + ((t4 + t5) + (t6 + t7));
            part[warp][el][lane] = s;
        }
        __syncwarp();
        if (lane < 16) {
            float s = 0.0f;
#pragma unroll
            for (int j = 0; j < 32; j++) s += part[warp][lane][j];
            en_s[wd][ebase + c0 + lane] = s;
        }
        __syncwarp();
    }
    __syncthreads();

    if (warp < 8) {
        float v0s = en_s[wd][lane];
        float v1s = en_s[wd][lane + 32];
        float v2s = en_s[wd][lane + 64];
        float v3s = en_s[wd][lane + 96];
        float m = fmaxf(fmaxf(v0s, v1s), fmaxf(v2s, v3s));
#pragma unroll
        for (int o = 16; o > 0; o >>= 1)
            m = fmaxf(m, __shfl_xor_sync(0xffffffffu, m, o));
        float e0v = __expf(v0s - m), e1v = __expf(v1s - m);
        float e2v = __expf(v2s - m), e3v = __expf(v3s - m);
        float s = e0v + e1v + e2v + e3v;
#pragma unroll
        for (int o = 16; o > 0; o >>= 1)
            s += __shfl_xor_sync(0xffffffffu, s, o);
        float inv = __fdividef(1.0f, s);
        float p0 = e0v * inv, p1 = e1v * inv, p2 = e2v * inv, p3 = e3v * inv;
        pT_s[lane     ][wd] = p0;
        pT_s[lane + 32][wd] = p1;
        pT_s[lane + 64][wd] = p2;
        pT_s[lane + 96][wd] = p3;
        float* eo = e_out + ((b * TD_) + d) * TE_;
        eo[lane]      = p0;
        eo[lane + 32] = p1;
        eo[lane + 64] = p2;
        eo[lane + 96] = p3;
    }
    __syncthreads();

    {
        const int h = tid & 255;
        const int half = tid >> 8;
        float acc[8];
#pragma unroll
        for (int j = 0; j < 8; j++) acc[j] = 0.0f;
        const float* eb = g_ortho + (b * TE_ + half * 64) * H_ + h;
        const float (*pp)[9] = &pT_s[half * 64];
#pragma unroll 4
        for (int e = 0; e < 64; e++) {
            float x = eb[e * H_];
#pragma unroll
            for (int j = 0; j < 8; j++)
                acc[j] = fmaf(pp[e][j], x, acc[j]);
        }
        if (half == 1) {
#pragma unroll
            for (int j = 0; j < 8; j++) cpart[j][h] = acc[j];
        }
        __syncthreads();
        if (half == 0) {
#pragma unroll
            for (int j = 0; j < 8; j++)
                c_out[((b * TD_) + (d0 + j)) * H_ + h] = acc[j] + cpart[j][h];
        }
    }
}

// ---------------------------------------------------------------------------
extern "C" void kernel_launch(void* const* d_in, const int* in_sizes, int n_in,
                              void* d_out, int out_size) {
    const float* enc = (const float*)d_in[0];   // [16,128,256]
    const float* dec = (const float*)d_in[1];   // [16,128,256]
    const float* Wa  = (const float*)d_in[2];   // [256,256]
    const float* Ua  = (const float*)d_in[3];   // [256,256]
    const float* Va  = (const float*)d_in[4];   // [256,1]

    float* out   = (float*)d_out;
    float* c_out = out;                          // [16,128,256]
    float* e_out = out + B_ * TD_ * H_;          // [16,128,128]

    k1_kernel<<<dim3(4, 32, 3), 256>>>(enc, dec, Wa, Ua);
    k2_kernel<<<128, 256>>>();
    attn_kernel<<<dim3(TD_ / 8, B_), 512>>>(Va, c_out, e_out);
}

// round 8
// speedup vs baseline: 3.1510x; 1.1134x over previous
#include <cuda_runtime.h>
#include <cuda_bf16.h>

// Problem constants
#define B_   16
#define TE_  128
#define TD_  128
#define H_   256

#define BM 128
#define BN 64
#define BK 16

// Scratch (device globals)
__device__ float g_ortho[B_ * TE_ * H_];   // enc - cumsum_excl(enc)
__device__ float g_was  [B_ * TE_ * H_];   // scanned enc@Wa
__device__ float g_uah  [B_ * TD_ * H_];   // dec @ U_a

__device__ __forceinline__ float tanh_fast(float x) {
    float y;
    asm("tanh.approx.f32 %0, %1;" : "=f"(y) : "f"(x));
    return y;
}

// ---------------------------------------------------------------------------
// Scan block: out[b, t, hg*32+hl] = in[b,t,..] - sum_{t'<t} in[b,t',..]
// ---------------------------------------------------------------------------
__device__ __forceinline__ void scan_block(const float* __restrict__ in,
                                           float* __restrict__ out,
                                           int b, int hg, float* sm /*>=128*33*/) {
    const int tid  = threadIdx.x;
    const int warp = tid >> 5;
    const int lane = tid & 31;

    const float* base = in + (b * TE_) * H_ + hg * 32;
#pragma unroll
    for (int k = 0; k < 16; k++) {
        int idx = tid + k * 256;
        int t = idx >> 5, hl = idx & 31;
        sm[t * 33 + hl] = base[t * H_ + hl];
    }
    __syncthreads();

#pragma unroll
    for (int c = 0; c < 4; c++) {
        int h = warp * 4 + c;
        float a0 = sm[(4 * lane + 0) * 33 + h];
        float a1 = sm[(4 * lane + 1) * 33 + h];
        float a2 = sm[(4 * lane + 2) * 33 + h];
        float a3 = sm[(4 * lane + 3) * 33 + h];
        float L = (a0 + a1) + (a2 + a3);
        float sc = L;
#pragma unroll
        for (int o = 1; o < 32; o <<= 1) {
            float v = __shfl_up_sync(0xffffffffu, sc, o);
            if (lane >= o) sc += v;
        }
        float p = sc - L;
        float o0 = a0 - p; p += a0;
        float o1 = a1 - p; p += a1;
        float o2 = a2 - p; p += a2;
        float o3 = a3 - p;
        sm[(4 * lane + 0) * 33 + h] = o0;
        sm[(4 * lane + 1) * 33 + h] = o1;
        sm[(4 * lane + 2) * 33 + h] = o2;
        sm[(4 * lane + 3) * 33 + h] = o3;
    }
    __syncthreads();

    float* obase = out + (b * TE_) * H_ + hg * 32;
#pragma unroll
    for (int k = 0; k < 16; k++) {
        int idx = tid + k * 256;
        int t = idx >> 5, hl = idx & 31;
        obase[t * H_ + hl] = sm[t * 33 + hl];
    }
}

// ---------------------------------------------------------------------------
// K1:
//   z=0 -> g_was = scan(enc @ Wa)     (scan fused in epilogue, BM=1 batch)
//   z=1 -> g_uah = dec @ Ua
//   z=2 -> g_ortho = enc - cumsum_excl(enc)   (2 scan units per block)
// GEMM: 128x64 tile, BK=16, 256 threads, 8x4 microtile, double-buffered.
// ---------------------------------------------------------------------------
__global__ __launch_bounds__(256) void k1_kernel(const float* __restrict__ enc,
                                                 const float* __restrict__ dec,
                                                 const float* __restrict__ Wa,
                                                 const float* __restrict__ Ua) {
    __shared__ __align__(16) float sm[8320];   // 33.3KB, multi-purpose

    if (blockIdx.z == 2) {
        int lin = blockIdx.y * 4 + blockIdx.x;        // 0..63
        scan_block(enc, g_ortho, lin >> 3, lin & 7, sm);
        __syncthreads();
        int lin2 = lin + 64;                          // 64..127
        scan_block(enc, g_ortho, lin2 >> 3, lin2 & 7, sm);
        return;
    }

    const int z = blockIdx.z;
    const float* A = z ? dec : enc;
    const float* W = z ? Ua  : Wa;
    float*       C = z ? g_uah : g_was;

    // smem tiles: As[2][16][132] at 0 (4224 floats), Bs[2][16][68] at 4224
    float (*As)[132] = (float (*)[132])sm;            // index [buf*16+kk]
    float (*Bs)[68]  = (float (*)[68])(sm + 4224);

    const int bm = blockIdx.y * BM;    // y: 0..15  (= batch index for z=0)
    const int bn = blockIdx.x * BN;    // x: 0..3
    const int tid = threadIdx.x;
    const int warp = tid >> 5;
    const int lane = tid & 31;
    const int tr = tid >> 4;           // 0..15 -> m rows tr*8..tr*8+7
    const int tc = tid & 15;           // 0..15 -> n cols tc*4..tc*4+3

    // Load coords: A rows r0=tid>>2 and r0+64, k-quad q=tid&3
    const int r0 = tid >> 2;
    const int qa = tid & 3;
    const int lbk = tid >> 4;          // B k-row 0..15
    const int lbq = tid & 15;          // B n-quad

    float acc[8][4];
#pragma unroll
    for (int i = 0; i < 8; i++)
#pragma unroll
        for (int j = 0; j < 4; j++) acc[i][j] = 0.0f;

    // Prefetch tile 0
    float4 pa0 = *(const float4*)&A[(bm + r0) * 256 + qa * 4];
    float4 pa1 = *(const float4*)&A[(bm + r0 + 64) * 256 + qa * 4];
    float4 pb  = *(const float4*)&W[lbk * 256 + bn + lbq * 4];

    // STS tile 0 -> buf 0
    As[qa * 4 + 0][r0] = pa0.x;  As[qa * 4 + 1][r0] = pa0.y;
    As[qa * 4 + 2][r0] = pa0.z;  As[qa * 4 + 3][r0] = pa0.w;
    As[qa * 4 + 0][r0 + 64] = pa1.x;  As[qa * 4 + 1][r0 + 64] = pa1.y;
    As[qa * 4 + 2][r0 + 64] = pa1.z;  As[qa * 4 + 3][r0 + 64] = pa1.w;
    *(float4*)&Bs[lbk][lbq * 4] = pb;
    __syncthreads();

#pragma unroll 1
    for (int kt = 0; kt < 16; kt++) {
        if (kt < 15) {
            int k0 = (kt + 1) * BK;
            pa0 = *(const float4*)&A[(bm + r0) * 256 + k0 + qa * 4];
            pa1 = *(const float4*)&A[(bm + r0 + 64) * 256 + k0 + qa * 4];
            pb  = *(const float4*)&W[(k0 + lbk) * 256 + bn + lbq * 4];
        }
        const int cb = (kt & 1) * 16;
#pragma unroll
        for (int kk = 0; kk < 16; kk++) {
            float4 aLo = *(const float4*)&As[cb + kk][tr * 8];
            float4 aHi = *(const float4*)&As[cb + kk][tr * 8 + 4];
            float4 b4  = *(const float4*)&Bs[cb + kk][tc * 4];
            float am[8] = {aLo.x, aLo.y, aLo.z, aLo.w, aHi.x, aHi.y, aHi.z, aHi.w};
#pragma unroll
            for (int i = 0; i < 8; i++) {
                acc[i][0] = fmaf(am[i], b4.x, acc[i][0]);
                acc[i][1] = fmaf(am[i], b4.y, acc[i][1]);
                acc[i][2] = fmaf(am[i], b4.z, acc[i][2]);
                acc[i][3] = fmaf(am[i], b4.w, acc[i][3]);
            }
        }
        if (kt < 15) {
            const int nb = ((kt + 1) & 1) * 16;
            As[nb + qa * 4 + 0][r0] = pa0.x;  As[nb + qa * 4 + 1][r0] = pa0.y;
            As[nb + qa * 4 + 2][r0] = pa0.z;  As[nb + qa * 4 + 3][r0] = pa0.w;
            As[nb + qa * 4 + 0][r0 + 64] = pa1.x;  As[nb + qa * 4 + 1][r0 + 64] = pa1.y;
            As[nb + qa * 4 + 2][r0 + 64] = pa1.z;  As[nb + qa * 4 + 3][r0 + 64] = pa1.w;
            *(float4*)&Bs[nb + lbk][lbq * 4] = pb;
            __syncthreads();
        }
    }

    if (z == 1) {
        // Plain store
#pragma unroll
        for (int i = 0; i < 8; i++) {
            float4 o;
            o.x = acc[i][0]; o.y = acc[i][1]; o.z = acc[i][2]; o.w = acc[i][3];
            *(float4*)&C[(bm + tr * 8 + i) * 256 + bn + tc * 4] = o;
        }
        return;
    }

    // z == 0: fused scan epilogue. This block owns batch b = bm/128, all T=128
    // rows, cols bn..bn+63. was = Y - excl_cumsum_t(Y).
    __syncthreads();                       // done with tile buffers (aliased)
    float* sb = sm;                        // scan buffer, stride 65
#pragma unroll
    for (int i = 0; i < 8; i++) {
        int t = tr * 8 + i;
#pragma unroll
        for (int j = 0; j < 4; j++)
            sb[t * 65 + tc * 4 + j] = acc[i][j];
    }
    __syncthreads();

#pragma unroll
    for (int c = 0; c < 8; c++) {
        int col = warp * 8 + c;
        float a0 = sb[(4 * lane + 0) * 65 + col];
        float a1 = sb[(4 * lane + 1) * 65 + col];
        float a2 = sb[(4 * lane + 2) * 65 + col];
        float a3 = sb[(4 * lane + 3) * 65 + col];
        float L = (a0 + a1) + (a2 + a3);
        float sc = L;
#pragma unroll
        for (int o = 1; o < 32; o <<= 1) {
            float v = __shfl_up_sync(0xffffffffu, sc, o);
            if (lane >= o) sc += v;
        }
        float p = sc - L;
        float o0 = a0 - p; p += a0;
        float o1 = a1 - p; p += a1;
        float o2 = a2 - p; p += a2;
        float o3 = a3 - p;
        sb[(4 * lane + 0) * 65 + col] = o0;
        sb[(4 * lane + 1) * 65 + col] = o1;
        sb[(4 * lane + 2) * 65 + col] = o2;
        sb[(4 * lane + 3) * 65 + col] = o3;
    }
    __syncthreads();

#pragma unroll
    for (int k = 0; k < 32; k++) {
        int idx = tid + k * 256;
        int t = idx >> 6, c = idx & 63;
        C[(bm + t) * 256 + bn + c] = sb[t * 65 + c];
    }
}

// ---------------------------------------------------------------------------
// K3: fused energy + softmax + context.
// ---------------------------------------------------------------------------
__global__ __launch_bounds__(512) void attn_kernel(const float* __restrict__ Va,
                                                   float* __restrict__ c_out,
                                                   float* __restrict__ e_out) {
    const int b    = blockIdx.y;
    const int d0   = blockIdx.x * 8;
    const int tid  = threadIdx.x;
    const int warp = tid >> 5;
    const int lane = tid & 31;
    const int wd   = warp & 7;
    const int eh   = warp >> 3;

    __shared__ float part[16][16][33];
    __shared__ float en_s[8][TE_];
    __shared__ float pT_s[TE_][9];
    __shared__ float cpart[8][256];

    const int d = d0 + wd;

    const float4 v0 = *(const float4*)(Va + 4 * lane);
    const float4 v1 = *(const float4*)(Va + 128 + 4 * lane);
    const float* urow = g_uah + ((b * TD_) + d) * H_;
    const float4 u0 = *(const float4*)(urow + 4 * lane);
    const float4 u1 = *(const float4*)(urow + 128 + 4 * lane);

    const float* wbase = g_was + (b * TE_) * H_;
    const int ebase = eh * 64;

    for (int c0 = 0; c0 < 64; c0 += 16) {
#pragma unroll 4
        for (int el = 0; el < 16; el++) {
            const float* wr = wbase + (ebase + c0 + el) * H_;
            float4 w0 = *(const float4*)(wr + 4 * lane);
            float4 w1 = *(const float4*)(wr + 128 + 4 * lane);
            float t0 = tanh_fast(w0.x + u0.x) * v0.x;
            float t1 = tanh_fast(w0.y + u0.y) * v0.y;
            float t2 = tanh_fast(w0.z + u0.z) * v0.z;
            float t3 = tanh_fast(w0.w + u0.w) * v0.w;
            float t4 = tanh_fast(w1.x + u1.x) * v1.x;
            float t5 = tanh_fast(w1.y + u1.y) * v1.y;
            float t6 = tanh_fast(w1.z + u1.z) * v1.z;
            float t7 = tanh_fast(w1.w + u1.w) * v1.w;
            float s = ((t0 + t1) + (t2 + t3)) + ((t4 + t5) + (t6 + t7));
            part[warp][el][lane] = s;
        }
        __syncwarp();
        if (lane < 16) {
            float s = 0.0f;
#pragma unroll
            for (int j = 0; j < 32; j++) s += part[warp][lane][j];
            en_s[wd][ebase + c0 + lane] = s;
        }
        __syncwarp();
    }
    __syncthreads();

    if (warp < 8) {
        float v0s = en_s[wd][lane];
        float v1s = en_s[wd][lane + 32];
        float v2s = en_s[wd][lane + 64];
        float v3s = en_s[wd][lane + 96];
        float m = fmaxf(fmaxf(v0s, v1s), fmaxf(v2s, v3s));
#pragma unroll
        for (int o = 16; o > 0; o >>= 1)
            m = fmaxf(m, __shfl_xor_sync(0xffffffffu, m, o));
        float e0v = __expf(v0s - m), e1v = __expf(v1s - m);
        float e2v = __expf(v2s - m), e3v = __expf(v3s - m);
        float s = e0v + e1v + e2v + e3v;
#pragma unroll
        for (int o = 16; o > 0; o >>= 1)
            s += __shfl_xor_sync(0xffffffffu, s, o);
        float inv = __fdividef(1.0f, s);
        float p0 = e0v * inv, p1 = e1v * inv, p2 = e2v * inv, p3 = e3v * inv;
        pT_s[lane     ][wd] = p0;
        pT_s[lane + 32][wd] = p1;
        pT_s[lane + 64][wd] = p2;
        pT_s[lane + 96][wd] = p3;
        float* eo = e_out + ((b * TD_) + d) * TE_;
        eo[lane]      = p0;
        eo[lane + 32] = p1;
        eo[lane + 64] = p2;
        eo[lane + 96] = p3;
    }
    __syncthreads();

    {
        const int h = tid & 255;
        const int half = tid >> 8;
        float acc[8];
#pragma unroll
        for (int j = 0; j < 8; j++) acc[j] = 0.0f;
        const float* eb = g_ortho + (b * TE_ + half * 64) * H_ + h;
        const float (*pp)[9] = &pT_s[half * 64];
#pragma unroll 4
        for (int e = 0; e < 64; e++) {
            float x = eb[e * H_];
#pragma unroll
            for (int j = 0; j < 8; j++)
                acc[j] = fmaf(pp[e][j], x, acc[j]);
        }
        if (half == 1) {
#pragma unroll
            for (int j = 0; j < 8; j++) cpart[j][h] = acc[j];
        }
        __syncthreads();
        if (half == 0) {
#pragma unroll
            for (int j = 0; j < 8; j++)
                c_out[((b * TD_) + (d0 + j)) * H_ + h] = acc[j] + cpart[j][h];
        }
    }
}

// ---------------------------------------------------------------------------
extern "C" void kernel_launch(void* const* d_in, const int* in_sizes, int n_in,
                              void* d_out, int out_size) {
    const float* enc = (const float*)d_in[0];   // [16,128,256]
    const float* dec = (const float*)d_in[1];   // [16,128,256]
    const float* Wa  = (const float*)d_in[2];   // [256,256]
    const float* Ua  = (const float*)d_in[3];   // [256,256]
    const float* Va  = (const float*)d_in[4];   // [256,1]

    float* out   = (float*)d_out;
    float* c_out = out;                          // [16,128,256]
    float* e_out = out + B_ * TD_ * H_;          // [16,128,128]

    k1_kernel<<<dim3(4, 16, 3), 256>>>(enc, dec, Wa, Ua);
    attn_kernel<<<dim3(TD_ / 8, B_), 512>>>(Va, c_out, e_out);
}

// round 9
// speedup vs baseline: 3.1646x; 1.0043x over previous
#include <cuda_runtime.h>
#include <cuda_bf16.h>

// Problem constants
#define B_   16
#define TE_  128
#define TD_  128
#define H_   256

#define BM 128
#define BN 64
#define BK 16

// Scratch (device globals)
__device__ float g_ortho[B_ * TE_ * H_];   // enc - cumsum_excl(enc)
__device__ float g_was  [B_ * TE_ * H_];   // scanned enc@Wa
__device__ float g_uah  [B_ * TD_ * H_];   // dec @ U_a

__device__ __forceinline__ float tanh_fast(float x) {
    float y;
    asm("tanh.approx.f32 %0, %1;" : "=f"(y) : "f"(x));
    return y;
}

// ---------------------------------------------------------------------------
// Scan block: out[b, t, hg*32+hl] = in[b,t,..] - sum_{t'<t} in[b,t',..]
// ---------------------------------------------------------------------------
__device__ __forceinline__ void scan_block(const float* __restrict__ in,
                                           float* __restrict__ out,
                                           int b, int hg, float* sm /*>=128*33*/) {
    const int tid  = threadIdx.x;
    const int warp = tid >> 5;
    const int lane = tid & 31;

    const float* base = in + (b * TE_) * H_ + hg * 32;
#pragma unroll
    for (int k = 0; k < 16; k++) {
        int idx = tid + k * 256;
        int t = idx >> 5, hl = idx & 31;
        sm[t * 33 + hl] = base[t * H_ + hl];
    }
    __syncthreads();

#pragma unroll
    for (int c = 0; c < 4; c++) {
        int h = warp * 4 + c;
        float a0 = sm[(4 * lane + 0) * 33 + h];
        float a1 = sm[(4 * lane + 1) * 33 + h];
        float a2 = sm[(4 * lane + 2) * 33 + h];
        float a3 = sm[(4 * lane + 3) * 33 + h];
        float L = (a0 + a1) + (a2 + a3);
        float sc = L;
#pragma unroll
        for (int o = 1; o < 32; o <<= 1) {
            float v = __shfl_up_sync(0xffffffffu, sc, o);
            if (lane >= o) sc += v;
        }
        float p = sc - L;
        float o0 = a0 - p; p += a0;
        float o1 = a1 - p; p += a1;
        float o2 = a2 - p; p += a2;
        float o3 = a3 - p;
        sm[(4 * lane + 0) * 33 + h] = o0;
        sm[(4 * lane + 1) * 33 + h] = o1;
        sm[(4 * lane + 2) * 33 + h] = o2;
        sm[(4 * lane + 3) * 33 + h] = o3;
    }
    __syncthreads();

    float* obase = out + (b * TE_) * H_ + hg * 32;
#pragma unroll
    for (int k = 0; k < 16; k++) {
        int idx = tid + k * 256;
        int t = idx >> 5, hl = idx & 31;
        obase[t * H_ + hl] = sm[t * 33 + hl];
    }
}

// ---------------------------------------------------------------------------
// K1:
//   z=0 -> g_was = scan(enc @ Wa)   (scan fused in epilogue)
//   z=1 -> g_uah = dec @ Ua
//   z=2 -> g_ortho = enc - cumsum_excl(enc)
// ---------------------------------------------------------------------------
__global__ __launch_bounds__(256) void k1_kernel(const float* __restrict__ enc,
                                                 const float* __restrict__ dec,
                                                 const float* __restrict__ Wa,
                                                 const float* __restrict__ Ua) {
    __shared__ __align__(16) float sm[8320];

    if (blockIdx.z == 2) {
        int lin = blockIdx.y * 4 + blockIdx.x;
        scan_block(enc, g_ortho, lin >> 3, lin & 7, sm);
        __syncthreads();
        int lin2 = lin + 64;
        scan_block(enc, g_ortho, lin2 >> 3, lin2 & 7, sm);
        return;
    }

    const int z = blockIdx.z;
    const float* A = z ? dec : enc;
    const float* W = z ? Ua  : Wa;
    float*       C = z ? g_uah : g_was;

    float (*As)[132] = (float (*)[132])sm;
    float (*Bs)[68]  = (float (*)[68])(sm + 4224);

    const int bm = blockIdx.y * BM;
    const int bn = blockIdx.x * BN;
    const int tid = threadIdx.x;
    const int warp = tid >> 5;
    const int lane = tid & 31;
    const int tr = tid >> 4;
    const int tc = tid & 15;

    const int r0 = tid >> 2;
    const int qa = tid & 3;
    const int lbk = tid >> 4;
    const int lbq = tid & 15;

    float acc[8][4];
#pragma unroll
    for (int i = 0; i < 8; i++)
#pragma unroll
        for (int j = 0; j < 4; j++) acc[i][j] = 0.0f;

    float4 pa0 = *(const float4*)&A[(bm + r0) * 256 + qa * 4];
    float4 pa1 = *(const float4*)&A[(bm + r0 + 64) * 256 + qa * 4];
    float4 pb  = *(const float4*)&W[lbk * 256 + bn + lbq * 4];

    As[qa * 4 + 0][r0] = pa0.x;  As[qa * 4 + 1][r0] = pa0.y;
    As[qa * 4 + 2][r0] = pa0.z;  As[qa * 4 + 3][r0] = pa0.w;
    As[qa * 4 + 0][r0 + 64] = pa1.x;  As[qa * 4 + 1][r0 + 64] = pa1.y;
    As[qa * 4 + 2][r0 + 64] = pa1.z;  As[qa * 4 + 3][r0 + 64] = pa1.w;
    *(float4*)&Bs[lbk][lbq * 4] = pb;
    __syncthreads();

#pragma unroll 1
    for (int kt = 0; kt < 16; kt++) {
        if (kt < 15) {
            int k0 = (kt + 1) * BK;
            pa0 = *(const float4*)&A[(bm + r0) * 256 + k0 + qa * 4];
            pa1 = *(const float4*)&A[(bm + r0 + 64) * 256 + k0 + qa * 4];
            pb  = *(const float4*)&W[(k0 + lbk) * 256 + bn + lbq * 4];
        }
        const int cb = (kt & 1) * 16;
#pragma unroll
        for (int kk = 0; kk < 16; kk++) {
            float4 aLo = *(const float4*)&As[cb + kk][tr * 8];
            float4 aHi = *(const float4*)&As[cb + kk][tr * 8 + 4];
            float4 b4  = *(const float4*)&Bs[cb + kk][tc * 4];
            float am[8] = {aLo.x, aLo.y, aLo.z, aLo.w, aHi.x, aHi.y, aHi.z, aHi.w};
#pragma unroll
            for (int i = 0; i < 8; i++) {
                acc[i][0] = fmaf(am[i], b4.x, acc[i][0]);
                acc[i][1] = fmaf(am[i], b4.y, acc[i][1]);
                acc[i][2] = fmaf(am[i], b4.z, acc[i][2]);
                acc[i][3] = fmaf(am[i], b4.w, acc[i][3]);
            }
        }
        if (kt < 15) {
            const int nb = ((kt + 1) & 1) * 16;
            As[nb + qa * 4 + 0][r0] = pa0.x;  As[nb + qa * 4 + 1][r0] = pa0.y;
            As[nb + qa * 4 + 2][r0] = pa0.z;  As[nb + qa * 4 + 3][r0] = pa0.w;
            As[nb + qa * 4 + 0][r0 + 64] = pa1.x;  As[nb + qa * 4 + 1][r0 + 64] = pa1.y;
            As[nb + qa * 4 + 2][r0 + 64] = pa1.z;  As[nb + qa * 4 + 3][r0 + 64] = pa1.w;
            *(float4*)&Bs[nb + lbk][lbq * 4] = pb;
            __syncthreads();
        }
    }

    if (z == 1) {
#pragma unroll
        for (int i = 0; i < 8; i++) {
            float4 o;
            o.x = acc[i][0]; o.y = acc[i][1]; o.z = acc[i][2]; o.w = acc[i][3];
            *(float4*)&C[(bm + tr * 8 + i) * 256 + bn + tc * 4] = o;
        }
        return;
    }

    // z == 0: fused scan epilogue
    __syncthreads();
    float* sb = sm;
#pragma unroll
    for (int i = 0; i < 8; i++) {
        int t = tr * 8 + i;
#pragma unroll
        for (int j = 0; j < 4; j++)
            sb[t * 65 + tc * 4 + j] = acc[i][j];
    }
    __syncthreads();

#pragma unroll
    for (int c = 0; c < 8; c++) {
        int col = warp * 8 + c;
        float a0 = sb[(4 * lane + 0) * 65 + col];
        float a1 = sb[(4 * lane + 1) * 65 + col];
        float a2 = sb[(4 * lane + 2) * 65 + col];
        float a3 = sb[(4 * lane + 3) * 65 + col];
        float L = (a0 + a1) + (a2 + a3);
        float sc = L;
#pragma unroll
        for (int o = 1; o < 32; o <<= 1) {
            float v = __shfl_up_sync(0xffffffffu, sc, o);
            if (lane >= o) sc += v;
        }
        float p = sc - L;
        float o0 = a0 - p; p += a0;
        float o1 = a1 - p; p += a1;
        float o2 = a2 - p; p += a2;
        float o3 = a3 - p;
        sb[(4 * lane + 0) * 65 + col] = o0;
        sb[(4 * lane + 1) * 65 + col] = o1;
        sb[(4 * lane + 2) * 65 + col] = o2;
        sb[(4 * lane + 3) * 65 + col] = o3;
    }
    __syncthreads();

#pragma unroll
    for (int k = 0; k < 32; k++) {
        int idx = tid + k * 256;
        int t = idx >> 6, c = idx & 63;
        C[(bm + t) * 256 + bn + c] = sb[t * 65 + c];
    }
}

// ---------------------------------------------------------------------------
// K3: fused energy + softmax + context.
// Block = (b, tile of 4 decoder positions), 512 threads = 16 warps.
// Warp w: d = d0 + (w&3), e-quarter = w>>2 (32 e each, chunks of 16).
// ---------------------------------------------------------------------------
__global__ __launch_bounds__(512) void attn_kernel(const float* __restrict__ Va,
                                                   float* __restrict__ c_out,
                                                   float* __restrict__ e_out) {
    const int b    = blockIdx.y;
    const int d0   = blockIdx.x * 4;
    const int tid  = threadIdx.x;
    const int warp = tid >> 5;
    const int lane = tid & 31;
    const int wd   = warp & 3;           // which d (0..3)
    const int eq   = warp >> 2;          // e-quarter (0..3)

    __shared__ float part[16][16][33];   // [warp][e_local][lane]
    __shared__ float en_s[4][TE_];       // energies [d_local][e]
    __shared__ float pT_s[TE_][5];       // transposed probs [e][d_local]
    __shared__ float cpart[4][256];      // context partials (upper half)

    const int d = d0 + wd;

    const float4 v0 = *(const float4*)(Va + 4 * lane);
    const float4 v1 = *(const float4*)(Va + 128 + 4 * lane);
    const float* urow = g_uah + ((b * TD_) + d) * H_;
    const float4 u0 = *(const float4*)(urow + 4 * lane);
    const float4 u1 = *(const float4*)(urow + 128 + 4 * lane);

    const float* wbase = g_was + (b * TE_) * H_;
    const int ebase = eq * 32;

    // ---- Energies: 32 e per warp, chunks of 16, FFMA-chain accumulate ----
#pragma unroll
    for (int c0 = 0; c0 < 32; c0 += 16) {
#pragma unroll 4
        for (int el = 0; el < 16; el++) {
            const float* wr = wbase + (ebase + c0 + el) * H_;
            float4 w0 = *(const float4*)(wr + 4 * lane);
            float4 w1 = *(const float4*)(wr + 128 + 4 * lane);
            float s = tanh_fast(w0.x + u0.x) * v0.x;
            s = fmaf(tanh_fast(w0.y + u0.y), v0.y, s);
            s = fmaf(tanh_fast(w0.z + u0.z), v0.z, s);
            s = fmaf(tanh_fast(w0.w + u0.w), v0.w, s);
            s = fmaf(tanh_fast(w1.x + u1.x), v1.x, s);
            s = fmaf(tanh_fast(w1.y + u1.y), v1.y, s);
            s = fmaf(tanh_fast(w1.z + u1.z), v1.z, s);
            s = fmaf(tanh_fast(w1.w + u1.w), v1.w, s);
            part[warp][el][lane] = s;
        }
        __syncwarp();
        if (lane < 16) {
            float s = 0.0f;
#pragma unroll
            for (int j = 0; j < 32; j++) s += part[warp][lane][j];
            en_s[wd][ebase + c0 + lane] = s;
        }
        __syncwarp();
    }
    __syncthreads();

    // ---- Softmax over e (warps 0-3, one d each) ----
    if (warp < 4) {
        float v0s = en_s[wd][lane];
        float v1s = en_s[wd][lane + 32];
        float v2s = en_s[wd][lane + 64];
        float v3s = en_s[wd][lane + 96];
        float m = fmaxf(fmaxf(v0s, v1s), fmaxf(v2s, v3s));
#pragma unroll
        for (int o = 16; o > 0; o >>= 1)
            m = fmaxf(m, __shfl_xor_sync(0xffffffffu, m, o));
        float e0v = __expf(v0s - m), e1v = __expf(v1s - m);
        float e2v = __expf(v2s - m), e3v = __expf(v3s - m);
        float s = e0v + e1v + e2v + e3v;
#pragma unroll
        for (int o = 16; o > 0; o >>= 1)
            s += __shfl_xor_sync(0xffffffffu, s, o);
        float inv = __fdividef(1.0f, s);
        float p0 = e0v * inv, p1 = e1v * inv, p2 = e2v * inv, p3 = e3v * inv;
        pT_s[lane     ][wd] = p0;
        pT_s[lane + 32][wd] = p1;
        pT_s[lane + 64][wd] = p2;
        pT_s[lane + 96][wd] = p3;
        float* eo = e_out + ((b * TD_) + d) * TE_;
        eo[lane]      = p0;
        eo[lane + 32] = p1;
        eo[lane + 64] = p2;
        eo[lane + 96] = p3;
    }
    __syncthreads();

    // ---- Context: c[d][h] = sum_e p[d][e] * ortho[b][e][h] ----
    {
        const int h = tid & 255;
        const int half = tid >> 8;
        float acc[4];
#pragma unroll
        for (int j = 0; j < 4; j++) acc[j] = 0.0f;
        const float* eb = g_ortho + (b * TE_ + half * 64) * H_ + h;
        const float (*pp)[5] = &pT_s[half * 64];
#pragma unroll 8
        for (int e = 0; e < 64; e++) {
            float x = eb[e * H_];
#pragma unroll
            for (int j = 0; j < 4; j++)
                acc[j] = fmaf(pp[e][j], x, acc[j]);
        }
        if (half == 1) {
#pragma unroll
            for (int j = 0; j < 4; j++) cpart[j][h] = acc[j];
        }
        __syncthreads();
        if (half == 0) {
#pragma unroll
            for (int j = 0; j < 4; j++)
                c_out[((b * TD_) + (d0 + j)) * H_ + h] = acc[j] + cpart[j][h];
        }
    }
}

// ---------------------------------------------------------------------------
extern "C" void kernel_launch(void* const* d_in, const int* in_sizes, int n_in,
                              void* d_out, int out_size) {
    const float* enc = (const float*)d_in[0];   // [16,128,256]
    const float* dec = (const float*)d_in[1];   // [16,128,256]
    const float* Wa  = (const float*)d_in[2];   // [256,256]
    const float* Ua  = (const float*)d_in[3];   // [256,256]
    const float* Va  = (const float*)d_in[4];   // [256,1]

    float* out   = (float*)d_out;
    float* c_out = out;                          // [16,128,256]
    float* e_out = out + B_ * TD_ * H_;          // [16,128,128]

    k1_kernel<<<dim3(4, 16, 3), 256>>>(enc, dec, Wa, Ua);
    attn_kernel<<<dim3(TD_ / 4, B_), 512>>>(Va, c_out, e_out);
}

// round 10
// speedup vs baseline: 3.2972x; 1.0419x over previous
#include <cuda_runtime.h>
#include <cuda_bf16.h>

// Problem constants
#define B_   16
#define TE_  128
#define TD_  128
#define H_   256

#define BM 128
#define BN 64
#define BK 16

// Scratch (device globals)
__device__ float g_ortho[B_ * TE_ * H_];   // enc - cumsum_excl(enc)
__device__ float g_was  [B_ * TE_ * H_];   // scanned enc@Wa
__device__ float g_uah  [B_ * TD_ * H_];   // dec @ U_a

__device__ __forceinline__ float tanh_fast(float x) {
    float y;
    asm("tanh.approx.f32 %0, %1;" : "=f"(y) : "f"(x));
    return y;
}

// ---------------------------------------------------------------------------
// Scan block: out[b, t, hg*32+hl] = in[b,t,..] - sum_{t'<t} in[b,t',..]
// ---------------------------------------------------------------------------
__device__ __forceinline__ void scan_block(const float* __restrict__ in,
                                           float* __restrict__ out,
                                           int b, int hg, float* sm /*>=128*33*/) {
    const int tid  = threadIdx.x;
    const int warp = tid >> 5;
    const int lane = tid & 31;

    const float* base = in + (b * TE_) * H_ + hg * 32;
#pragma unroll
    for (int k = 0; k < 16; k++) {
        int idx = tid + k * 256;
        int t = idx >> 5, hl = idx & 31;
        sm[t * 33 + hl] = base[t * H_ + hl];
    }
    __syncthreads();

#pragma unroll
    for (int c = 0; c < 4; c++) {
        int h = warp * 4 + c;
        float a0 = sm[(4 * lane + 0) * 33 + h];
        float a1 = sm[(4 * lane + 1) * 33 + h];
        float a2 = sm[(4 * lane + 2) * 33 + h];
        float a3 = sm[(4 * lane + 3) * 33 + h];
        float L = (a0 + a1) + (a2 + a3);
        float sc = L;
#pragma unroll
        for (int o = 1; o < 32; o <<= 1) {
            float v = __shfl_up_sync(0xffffffffu, sc, o);
            if (lane >= o) sc += v;
        }
        float p = sc - L;
        float o0 = a0 - p; p += a0;
        float o1 = a1 - p; p += a1;
        float o2 = a2 - p; p += a2;
        float o3 = a3 - p;
        sm[(4 * lane + 0) * 33 + h] = o0;
        sm[(4 * lane + 1) * 33 + h] = o1;
        sm[(4 * lane + 2) * 33 + h] = o2;
        sm[(4 * lane + 3) * 33 + h] = o3;
    }
    __syncthreads();

    float* obase = out + (b * TE_) * H_ + hg * 32;
#pragma unroll
    for (int k = 0; k < 16; k++) {
        int idx = tid + k * 256;
        int t = idx >> 5, hl = idx & 31;
        obase[t * H_ + hl] = sm[t * 33 + hl];
    }
}

// ---------------------------------------------------------------------------
// K1:
//   z=0 -> g_was = scan(enc @ Wa)   (scan fused in epilogue)
//   z=1 -> g_uah = dec @ Ua
//   z=2 -> g_ortho = enc - cumsum_excl(enc)
// ---------------------------------------------------------------------------
__global__ __launch_bounds__(256) void k1_kernel(const float* __restrict__ enc,
                                                 const float* __restrict__ dec,
                                                 const float* __restrict__ Wa,
                                                 const float* __restrict__ Ua) {
    __shared__ __align__(16) float sm[8320];

    if (blockIdx.z == 2) {
        int lin = blockIdx.y * 4 + blockIdx.x;
        scan_block(enc, g_ortho, lin >> 3, lin & 7, sm);
        __syncthreads();
        int lin2 = lin + 64;
        scan_block(enc, g_ortho, lin2 >> 3, lin2 & 7, sm);
        return;
    }

    const int z = blockIdx.z;
    const float* A = z ? dec : enc;
    const float* W = z ? Ua  : Wa;
    float*       C = z ? g_uah : g_was;

    float (*As)[132] = (float (*)[132])sm;
    float (*Bs)[68]  = (float (*)[68])(sm + 4224);

    const int bm = blockIdx.y * BM;
    const int bn = blockIdx.x * BN;
    const int tid = threadIdx.x;
    const int warp = tid >> 5;
    const int lane = tid & 31;
    const int tr = tid >> 4;
    const int tc = tid & 15;

    const int r0 = tid >> 2;
    const int qa = tid & 3;
    const int lbk = tid >> 4;
    const int lbq = tid & 15;

    float acc[8][4];
#pragma unroll
    for (int i = 0; i < 8; i++)
#pragma unroll
        for (int j = 0; j < 4; j++) acc[i][j] = 0.0f;

    float4 pa0 = *(const float4*)&A[(bm + r0) * 256 + qa * 4];
    float4 pa1 = *(const float4*)&A[(bm + r0 + 64) * 256 + qa * 4];
    float4 pb  = *(const float4*)&W[lbk * 256 + bn + lbq * 4];

    As[qa * 4 + 0][r0] = pa0.x;  As[qa * 4 + 1][r0] = pa0.y;
    As[qa * 4 + 2][r0] = pa0.z;  As[qa * 4 + 3][r0] = pa0.w;
    As[qa * 4 + 0][r0 + 64] = pa1.x;  As[qa * 4 + 1][r0 + 64] = pa1.y;
    As[qa * 4 + 2][r0 + 64] = pa1.z;  As[qa * 4 + 3][r0 + 64] = pa1.w;
    *(float4*)&Bs[lbk][lbq * 4] = pb;
    __syncthreads();

#pragma unroll 1
    for (int kt = 0; kt < 16; kt++) {
        if (kt < 15) {
            int k0 = (kt + 1) * BK;
            pa0 = *(const float4*)&A[(bm + r0) * 256 + k0 + qa * 4];
            pa1 = *(const float4*)&A[(bm + r0 + 64) * 256 + k0 + qa * 4];
            pb  = *(const float4*)&W[(k0 + lbk) * 256 + bn + lbq * 4];
        }
        const int cb = (kt & 1) * 16;
#pragma unroll
        for (int kk = 0; kk < 16; kk++) {
            float4 aLo = *(const float4*)&As[cb + kk][tr * 8];
            float4 aHi = *(const float4*)&As[cb + kk][tr * 8 + 4];
            float4 b4  = *(const float4*)&Bs[cb + kk][tc * 4];
            float am[8] = {aLo.x, aLo.y, aLo.z, aLo.w, aHi.x, aHi.y, aHi.z, aHi.w};
#pragma unroll
            for (int i = 0; i < 8; i++) {
                acc[i][0] = fmaf(am[i], b4.x, acc[i][0]);
                acc[i][1] = fmaf(am[i], b4.y, acc[i][1]);
                acc[i][2] = fmaf(am[i], b4.z, acc[i][2]);
                acc[i][3] = fmaf(am[i], b4.w, acc[i][3]);
            }
        }
        if (kt < 15) {
            const int nb = ((kt + 1) & 1) * 16;
            As[nb + qa * 4 + 0][r0] = pa0.x;  As[nb + qa * 4 + 1][r0] = pa0.y;
            As[nb + qa * 4 + 2][r0] = pa0.z;  As[nb + qa * 4 + 3][r0] = pa0.w;
            As[nb + qa * 4 + 0][r0 + 64] = pa1.x;  As[nb + qa * 4 + 1][r0 + 64] = pa1.y;
            As[nb + qa * 4 + 2][r0 + 64] = pa1.z;  As[nb + qa * 4 + 3][r0 + 64] = pa1.w;
            *(float4*)&Bs[nb + lbk][lbq * 4] = pb;
            __syncthreads();
        }
    }

    if (z == 1) {
#pragma unroll
        for (int i = 0; i < 8; i++) {
            float4 o;
            o.x = acc[i][0]; o.y = acc[i][1]; o.z = acc[i][2]; o.w = acc[i][3];
            *(float4*)&C[(bm + tr * 8 + i) * 256 + bn + tc * 4] = o;
        }
        return;
    }

    // z == 0: fused scan epilogue
    __syncthreads();
    float* sb = sm;
#pragma unroll
    for (int i = 0; i < 8; i++) {
        int t = tr * 8 + i;
#pragma unroll
        for (int j = 0; j < 4; j++)
            sb[t * 65 + tc * 4 + j] = acc[i][j];
    }
    __syncthreads();

#pragma unroll
    for (int c = 0; c < 8; c++) {
        int col = warp * 8 + c;
        float a0 = sb[(4 * lane + 0) * 65 + col];
        float a1 = sb[(4 * lane + 1) * 65 + col];
        float a2 = sb[(4 * lane + 2) * 65 + col];
        float a3 = sb[(4 * lane + 3) * 65 + col];
        float L = (a0 + a1) + (a2 + a3);
        float sc = L;
#pragma unroll
        for (int o = 1; o < 32; o <<= 1) {
            float v = __shfl_up_sync(0xffffffffu, sc, o);
            if (lane >= o) sc += v;
        }
        float p = sc - L;
        float o0 = a0 - p; p += a0;
        float o1 = a1 - p; p += a1;
        float o2 = a2 - p; p += a2;
        float o3 = a3 - p;
        sb[(4 * lane + 0) * 65 + col] = o0;
        sb[(4 * lane + 1) * 65 + col] = o1;
        sb[(4 * lane + 2) * 65 + col] = o2;
        sb[(4 * lane + 3) * 65 + col] = o3;
    }
    __syncthreads();

#pragma unroll
    for (int k = 0; k < 32; k++) {
        int idx = tid + k * 256;
        int t = idx >> 6, c = idx & 63;
        C[(bm + t) * 256 + bn + c] = sb[t * 65 + c];
    }
}

// ---------------------------------------------------------------------------
// K2: energies + softmax only; writes e_out (probabilities).
// Block = (b, tile of 4 d), 512 threads = 16 warps.
// Warp w: d = d0 + (w&3), e-quarter = w>>2 (32 e each, chunks of 16).
// ---------------------------------------------------------------------------
__global__ __launch_bounds__(512) void energy_kernel(const float* __restrict__ Va,
                                                     float* __restrict__ e_out) {
    const int b    = blockIdx.y;
    const int d0   = blockIdx.x * 4;
    const int tid  = threadIdx.x;
    const int warp = tid >> 5;
    const int lane = tid & 31;
    const int wd   = warp & 3;
    const int eq   = warp >> 2;

    __shared__ float part[16][16][33];
    __shared__ float en_s[4][TE_];

    const int d = d0 + wd;

    const float4 v0 = *(const float4*)(Va + 4 * lane);
    const float4 v1 = *(const float4*)(Va + 128 + 4 * lane);
    const float* urow = g_uah + ((b * TD_) + d) * H_;
    const float4 u0 = *(const float4*)(urow + 4 * lane);
    const float4 u1 = *(const float4*)(urow + 128 + 4 * lane);

    const float* wbase = g_was + (b * TE_) * H_;
    const int ebase = eq * 32;

#pragma unroll
    for (int c0 = 0; c0 < 32; c0 += 16) {
#pragma unroll 4
        for (int el = 0; el < 16; el++) {
            const float* wr = wbase + (ebase + c0 + el) * H_;
            float4 w0 = *(const float4*)(wr + 4 * lane);
            float4 w1 = *(const float4*)(wr + 128 + 4 * lane);
            float s = tanh_fast(w0.x + u0.x) * v0.x;
            s = fmaf(tanh_fast(w0.y + u0.y), v0.y, s);
            s = fmaf(tanh_fast(w0.z + u0.z), v0.z, s);
            s = fmaf(tanh_fast(w0.w + u0.w), v0.w, s);
            s = fmaf(tanh_fast(w1.x + u1.x), v1.x, s);
            s = fmaf(tanh_fast(w1.y + u1.y), v1.y, s);
            s = fmaf(tanh_fast(w1.z + u1.z), v1.z, s);
            s = fmaf(tanh_fast(w1.w + u1.w), v1.w, s);
            part[warp][el][lane] = s;
        }
        __syncwarp();
        if (lane < 16) {
            float s = 0.0f;
#pragma unroll
            for (int j = 0; j < 32; j++) s += part[warp][lane][j];
            en_s[wd][ebase + c0 + lane] = s;
        }
        __syncwarp();
    }
    __syncthreads();

    // Softmax over e (warps 0-3, one d each), write probs to e_out
    if (warp < 4) {
        float v0s = en_s[wd][lane];
        float v1s = en_s[wd][lane + 32];
        float v2s = en_s[wd][lane + 64];
        float v3s = en_s[wd][lane + 96];
        float m = fmaxf(fmaxf(v0s, v1s), fmaxf(v2s, v3s));
#pragma unroll
        for (int o = 16; o > 0; o >>= 1)
            m = fmaxf(m, __shfl_xor_sync(0xffffffffu, m, o));
        float e0v = __expf(v0s - m), e1v = __expf(v1s - m);
        float e2v = __expf(v2s - m), e3v = __expf(v3s - m);
        float s = e0v + e1v + e2v + e3v;
#pragma unroll
        for (int o = 16; o > 0; o >>= 1)
            s += __shfl_xor_sync(0xffffffffu, s, o);
        float inv = __fdividef(1.0f, s);
        float* eo = e_out + ((b * TD_) + d) * TE_;
        eo[lane]      = e0v * inv;
        eo[lane + 32] = e1v * inv;
        eo[lane + 64] = e2v * inv;
        eo[lane + 96] = e3v * inv;
    }
}

// ---------------------------------------------------------------------------
// K3: context batched GEMM.  c_out[b] = P[b] (TD x TE) @ g_ortho[b] (TE x H)
// 64x64 tile, K=128 (e), 256 threads, 4x4 micro, double-buffered.
// ---------------------------------------------------------------------------
__global__ __launch_bounds__(256) void ctx_kernel(const float* __restrict__ P,
                                                  float* __restrict__ c_out) {
    __shared__ __align__(16) float sm[2 * 16 * 68 * 2];   // As[2]+Bs[2]

    float (*As)[68] = (float (*)[68])sm;              // [buf*16+kk][row]
    float (*Bs)[68] = (float (*)[68])(sm + 2 * 16 * 68);

    const int bz = blockIdx.z;                         // batch
    const int bm = blockIdx.y * 64;                    // d
    const int bn = blockIdx.x * 64;                    // h
    const int tid = threadIdx.x;
    const int tr = tid >> 4;
    const int tc = tid & 15;

    const float* A = P       + bz * TD_ * TE_;         // stride TE_=128
    const float* W = g_ortho + bz * TE_ * H_;          // stride H_=256
    float*       C = c_out   + bz * TD_ * H_;

    const int r0 = tid >> 2;       // A row 0..63
    const int qa = tid & 3;        // A k-quad
    const int lbk = tid >> 4;      // B e-row 0..15
    const int lbq = tid & 15;      // B h-quad

    float acc[4][4];
#pragma unroll
    for (int i = 0; i < 4; i++)
#pragma unroll
        for (int j = 0; j < 4; j++) acc[i][j] = 0.0f;

    float4 pa = *(const float4*)&A[(bm + r0) * TE_ + qa * 4];
    float4 pb = *(const float4*)&W[lbk * H_ + bn + lbq * 4];
    As[qa * 4 + 0][r0] = pa.x;  As[qa * 4 + 1][r0] = pa.y;
    As[qa * 4 + 2][r0] = pa.z;  As[qa * 4 + 3][r0] = pa.w;
    *(float4*)&Bs[lbk][lbq * 4] = pb;
    __syncthreads();

#pragma unroll 1
    for (int kt = 0; kt < 8; kt++) {
        if (kt < 7) {
            int k0 = (kt + 1) * 16;
            pa = *(const float4*)&A[(bm + r0) * TE_ + k0 + qa * 4];
            pb = *(const float4*)&W[(k0 + lbk) * H_ + bn + lbq * 4];
        }
        const int cb = (kt & 1) * 16;
#pragma unroll
        for (int kk = 0; kk < 16; kk++) {
            float4 a4 = *(const float4*)&As[cb + kk][tr * 4];
            float4 b4 = *(const float4*)&Bs[cb + kk][tc * 4];
            acc[0][0] = fmaf(a4.x, b4.x, acc[0][0]);
            acc[0][1] = fmaf(a4.x, b4.y, acc[0][1]);
            acc[0][2] = fmaf(a4.x, b4.z, acc[0][2]);
            acc[0][3] = fmaf(a4.x, b4.w, acc[0][3]);
            acc[1][0] = fmaf(a4.y, b4.x, acc[1][0]);
            acc[1][1] = fmaf(a4.y, b4.y, acc[1][1]);
            acc[1][2] = fmaf(a4.y, b4.z, acc[1][2]);
            acc[1][3] = fmaf(a4.y, b4.w, acc[1][3]);
            acc[2][0] = fmaf(a4.z, b4.x, acc[2][0]);
            acc[2][1] = fmaf(a4.z, b4.y, acc[2][1]);
            acc[2][2] = fmaf(a4.z, b4.z, acc[2][2]);
            acc[2][3] = fmaf(a4.z, b4.w, acc[2][3]);
            acc[3][0] = fmaf(a4.w, b4.x, acc[3][0]);
            acc[3][1] = fmaf(a4.w, b4.y, acc[3][1]);
            acc[3][2] = fmaf(a4.w, b4.z, acc[3][2]);
            acc[3][3] = fmaf(a4.w, b4.w, acc[3][3]);
        }
        if (kt < 7) {
            const int nb = ((kt + 1) & 1) * 16;
            As[nb + qa * 4 + 0][r0] = pa.x;  As[nb + qa * 4 + 1][r0] = pa.y;
            As[nb + qa * 4 + 2][r0] = pa.z;  As[nb + qa * 4 + 3][r0] = pa.w;
            *(float4*)&Bs[nb + lbk][lbq * 4] = pb;
            __syncthreads();
        }
    }

#pragma unroll
    for (int i = 0; i < 4; i++) {
        float4 o;
        o.x = acc[i][0]; o.y = acc[i][1]; o.z = acc[i][2]; o.w = acc[i][3];
        *(float4*)&C[(bm + tr * 4 + i) * H_ + bn + tc * 4] = o;
    }
}

// ---------------------------------------------------------------------------
extern "C" void kernel_launch(void* const* d_in, const int* in_sizes, int n_in,
                              void* d_out, int out_size) {
    const float* enc = (const float*)d_in[0];   // [16,128,256]
    const float* dec = (const float*)d_in[1];   // [16,128,256]
    const float* Wa  = (const float*)d_in[2];   // [256,256]
    const float* Ua  = (const float*)d_in[3];   // [256,256]
    const float* Va  = (const float*)d_in[4];   // [256,1]

    float* out   = (float*)d_out;
    float* c_out = out;                          // [16,128,256]
    float* e_out = out + B_ * TD_ * H_;          // [16,128,128]

    k1_kernel<<<dim3(4, 16, 3), 256>>>(enc, dec, Wa, Ua);
    energy_kernel<<<dim3(TD_ / 4, B_), 512>>>(Va, e_out);
    ctx_kernel<<<dim3(4, 2, 16), 256>>>(e_out, c_out);
}